// round 8
// baseline (speedup 1.0000x reference)
#include <cuda_runtime.h>
#include <cuda_bf16.h>
#include <math.h>
#include <stdint.h>
#include <stddef.h>

#define BATCH_N 65536
#define QD      256
#define PGRID   148

// ---------------- ptx helpers ---------------------------------------------------
__device__ __forceinline__ uint32_t smem_u32(const void* p) {
    uint32_t a;
    asm("{ .reg .u64 t; cvta.to.shared.u64 t, %1; cvt.u32.u64 %0, t; }" : "=r"(a) : "l"(p));
    return a;
}

#define CP_ASYNC16(dst, src) \
    asm volatile("cp.async.cg.shared.global [%0], [%1], 16;" :: "r"(dst), "l"(src) : "memory")
#define CP_COMMIT() asm volatile("cp.async.commit_group;" ::: "memory")
#define CP_WAIT1()  asm volatile("cp.async.wait_group 1;" ::: "memory")
#define CP_WAIT0()  asm volatile("cp.async.wait_group 0;" ::: "memory")

#define LDSM_X4(r, addr) \
    asm volatile("ldmatrix.sync.aligned.m8n8.x4.shared.b16 {%0,%1,%2,%3}, [%4];" \
        : "=r"((r)[0]), "=r"((r)[1]), "=r"((r)[2]), "=r"((r)[3]) : "r"(addr))

#define MMA_TF32(c, a, b0, b1) \
    asm volatile("mma.sync.aligned.m16n8k8.row.col.f32.tf32.tf32.f32 " \
        "{%0,%1,%2,%3}, {%4,%5,%6,%7}, {%8,%9}, {%0,%1,%2,%3};" \
        : "+f"((c)[0]), "+f"((c)[1]), "+f"((c)[2]), "+f"((c)[3]) \
        : "r"((a)[0]), "r"((a)[1]), "r"((a)[2]), "r"((a)[3]), "r"(b0), "r"(b1))

#define CVT_TF32(r) asm volatile("cvt.rna.tf32.f32 %0, %0;" : "+r"(r))

__device__ __forceinline__ float tf32r(float v) {
    asm("cvt.rna.tf32.f32 %0, %0;" : "+f"(v));
    return v;
}

__device__ __forceinline__ float tanh_fast(float x) {
    return 1.0f - 2.0f / (__expf(2.0f * x) + 1.0f);
}

// ---------------- scratch -------------------------------------------------------
static __device__ __align__(16) float g_h[(size_t)BATCH_N * 768];
static __device__ __align__(16) float g_f[3][(size_t)BATCH_N * QD];
static __device__ __align__(16) float g_wtf[3276800];
static __device__ __align__(16) float g_gate[4][8 * QD];

struct Epi {
    const float* bias;
    const float* cmat;
    const float* resmat;
    const float* lin; const float* p3; const float* p4; const float* p5;
    float alpha;
    int   blend;
};

enum { E_BIAS = 0, E_SILU = 1, E_TANH = 2, E_GATE = 3, E_NL = 4 };

#define ROWB 144                       // 128B data + 16B skew

template <int EPI>
__device__ __forceinline__ void epi_apply(float& x, int n, size_t co, const Epi& ep) {
    if (EPI == E_BIAS) {
        x += ep.bias[n];
    } else if (EPI == E_SILU) {
        x += ep.bias[n];
        x = x / (1.0f + __expf(-x));
    } else if (EPI == E_TANH) {
        x += ep.bias[n];
        x = tanh_fast(x);
    } else if (EPI == E_GATE) {
        const float c = ep.cmat[co];
        const float g = (ep.lin[n] * c
                         + 0.5f * __sinf(ep.p3[n] * c + ep.p4[n])
                         + 0.5f * __cosf(ep.p5[n] * c)) * 0.25f;
        x = (c + 0.3f * g + 0.2f * x) * (1.0f / 1.5f);
        if (ep.blend)
            x = ep.alpha * x + (1.0f - ep.alpha) * ep.resmat[co];
    } else if (EPI == E_NL) {
        x += ep.bias[n];
        const float c2 = ep.cmat[co];
        x = ep.alpha * (c2 + 0.1f * x) + (1.0f - ep.alpha) * ep.resmat[co];
    }
}

// ============ wide GEMM: persistent, CTA tile 256x128, 512 thr ==================
#define OP_A  (256 * ROWB)
#define OP_Bw (128 * ROWB)
#define STGW  (OP_A + OP_Bw)
#define NSTG  3
#define SMEM_DYN (NSTG * STGW)         // 165888

template <int EPI>
__global__ void __launch_bounds__(512, 1) gemm_wide(
    const float* __restrict__ A, int lda,
    const float* __restrict__ W, int ldb,
    float* __restrict__ C, int ldc, int K, int N, Epi ep)
{
    extern __shared__ __align__(16) char dyns[];
    const uint32_t sbase = smem_u32(dyns);

    const int tid  = threadIdx.x;
    const int wid  = tid >> 5, lane = tid & 31;
    const int wm   = (wid >> 2) * 64;
    const int wn   = (wid & 3) * 32;

    const int iters = K / 32;
    const int nbn   = N / 128;
    const int ntile = nbn * (BATCH_N / 256);
    int ntl = 0;
    for (int t = blockIdx.x; t < ntile; t += PGRID) ntl++;
    const int total = ntl * iters;

    const int crow = tid >> 3;
    const int ccol = (tid & 7) * 16;
    const int gcol = (tid & 7) * 4;

    auto load_stage = [&](int g) {
        const int ti = g / iters, it = g - ti * iters;
        const int tile = blockIdx.x + ti * PGRID;
        const int m0 = (tile / nbn) * 256;
        const int n0 = (tile % nbn) * 128;
        const int ko = it * 32;
        const uint32_t smA = sbase + (uint32_t)(g % NSTG) * STGW;
        const uint32_t smB = smA + OP_A;
        const float* ga = A + (size_t)(m0 + crow) * lda + ko + gcol;
        const float* gb = W + (size_t)(n0 + crow) * ldb + ko + gcol;
#pragma unroll
        for (int i = 0; i < 4; i++)
            CP_ASYNC16(smA + (uint32_t)(crow + i * 64) * ROWB + ccol, ga + (size_t)(i * 64) * lda);
#pragma unroll
        for (int i = 0; i < 2; i++)
            CP_ASYNC16(smB + (uint32_t)(crow + i * 64) * ROWB + ccol, gb + (size_t)(i * 64) * ldb);
        CP_COMMIT();
    };

    float acc[4][4][4];
    load_stage(0);
    if (total > 1) load_stage(1);

    const int lr = lane & 15, lc = lane >> 4;
    const int gid = lane >> 2, t4 = lane & 3;

    for (int g = 0; g < total; ++g) {
        const int it = g % iters;
        if (it == 0) {
#pragma unroll
            for (int i = 0; i < 4; i++)
#pragma unroll
                for (int j = 0; j < 4; j++)
#pragma unroll
                    for (int q = 0; q < 4; q++) acc[i][j][q] = 0.0f;
        }
        if (g + 2 < total) { CP_WAIT1(); } else { CP_WAIT0(); }
        __syncthreads();
        if (g + 2 < total) load_stage(g + 2);

        const uint32_t smA = sbase + (uint32_t)(g % NSTG) * STGW;
        const uint32_t smB = smA + OP_A;

#pragma unroll
        for (int ks = 0; ks < 4; ks++) {
            uint32_t a[4][4], b[2][4];
#pragma unroll
            for (int mt = 0; mt < 4; mt++) {
                LDSM_X4(a[mt], smA + (uint32_t)(wm + mt * 16 + lr) * ROWB + ks * 32 + lc * 16);
#pragma unroll
                for (int q = 0; q < 4; q++) CVT_TF32(a[mt][q]);
            }
#pragma unroll
            for (int bt = 0; bt < 2; bt++)
                LDSM_X4(b[bt], smB + (uint32_t)(wn + bt * 16 + lr) * ROWB + ks * 32 + lc * 16);
#pragma unroll
            for (int mt = 0; mt < 4; mt++)
#pragma unroll
                for (int nt = 0; nt < 4; nt++)
                    MMA_TF32(acc[mt][nt], a[mt], b[nt >> 1][nt & 1], b[nt >> 1][(nt & 1) + 2]);
        }

        if (it == iters - 1) {
            const int tile = blockIdx.x + (g / iters) * PGRID;
            const int m0 = (tile / nbn) * 256;
            const int n0 = (tile % nbn) * 128;
#pragma unroll
            for (int mt = 0; mt < 4; mt++) {
#pragma unroll
                for (int half = 0; half < 2; half++) {
                    const int m = m0 + wm + mt * 16 + gid + half * 8;
#pragma unroll
                    for (int nt = 0; nt < 4; nt++) {
                        const int n = n0 + wn + nt * 8 + t4 * 2;
                        const size_t co = (size_t)m * ldc + n;
                        float x0 = acc[mt][nt][half * 2];
                        float x1 = acc[mt][nt][half * 2 + 1];
                        epi_apply<EPI>(x0, n, co, ep);
                        epi_apply<EPI>(x1, n + 1, co + 1, ep);
                        *(float2*)&C[co] = make_float2(x0, x1);
                    }
                }
            }
        }
    }
}

// ============ n256 GEMM: persistent, CTA 128x256, 256 thr, warp 64x64 ===========
#define OP_An (128 * ROWB)
#define OP_Bn (256 * ROWB)
#define STGN  (OP_An + OP_Bn)          // 55296 -> 3* = 165888

template <int EPI, int NORM>
__global__ void __launch_bounds__(256, 1) gemm_n256(
    const float* __restrict__ A, int lda,
    const float* __restrict__ W, int ldb,
    float* __restrict__ C, int K, Epi ep)
{
    extern __shared__ __align__(16) char dyns[];
    __shared__ float s_red[128 * 4];
    const uint32_t sbase = smem_u32(dyns);

    const int tid  = threadIdx.x;
    const int wid  = tid >> 5, lane = tid & 31;
    const int wm   = (wid >> 2) * 64;      // 0 / 64
    const int wn   = (wid & 3) * 64;       // 0..192
    const int wcol = wid & 3;

    const int iters = K / 32;
    const int ntile = BATCH_N / 128;       // 512
    int ntl = 0;
    for (int t = blockIdx.x; t < ntile; t += PGRID) ntl++;
    const int total = ntl * iters;

    const int crow = tid >> 3;             // 0..31
    const int ccol = (tid & 7) * 16;
    const int gcol = (tid & 7) * 4;

    auto load_stage = [&](int g) {
        const int ti = g / iters, it = g - ti * iters;
        const int m0 = (blockIdx.x + ti * PGRID) * 128;
        const int ko = it * 32;
        const uint32_t smA = sbase + (uint32_t)(g % NSTG) * STGN;
        const uint32_t smB = smA + OP_An;
        const float* ga = A + (size_t)(m0 + crow) * lda + ko + gcol;
        const float* gb = W + (size_t)crow * ldb + ko + gcol;
#pragma unroll
        for (int i = 0; i < 4; i++)
            CP_ASYNC16(smA + (uint32_t)(crow + i * 32) * ROWB + ccol, ga + (size_t)(i * 32) * lda);
#pragma unroll
        for (int i = 0; i < 8; i++)
            CP_ASYNC16(smB + (uint32_t)(crow + i * 32) * ROWB + ccol, gb + (size_t)(i * 32) * ldb);
        CP_COMMIT();
    };

    float acc[4][8][4];
    load_stage(0);
    if (total > 1) load_stage(1);

    const int lr = lane & 15, lc = lane >> 4;
    const int gid = lane >> 2, t4 = lane & 3;

    for (int g = 0; g < total; ++g) {
        const int it = g % iters;
        if (it == 0) {
#pragma unroll
            for (int i = 0; i < 4; i++)
#pragma unroll
                for (int j = 0; j < 8; j++)
#pragma unroll
                    for (int q = 0; q < 4; q++) acc[i][j][q] = 0.0f;
        }
        if (g + 2 < total) { CP_WAIT1(); } else { CP_WAIT0(); }
        __syncthreads();
        if (g + 2 < total) load_stage(g + 2);

        const uint32_t smA = sbase + (uint32_t)(g % NSTG) * STGN;
        const uint32_t smB = smA + OP_An;

#pragma unroll
        for (int ks = 0; ks < 4; ks++) {
            uint32_t a[4][4], b[4][4];
#pragma unroll
            for (int mt = 0; mt < 4; mt++) {
                LDSM_X4(a[mt], smA + (uint32_t)(wm + mt * 16 + lr) * ROWB + ks * 32 + lc * 16);
#pragma unroll
                for (int q = 0; q < 4; q++) CVT_TF32(a[mt][q]);
            }
#pragma unroll
            for (int bt = 0; bt < 4; bt++)
                LDSM_X4(b[bt], smB + (uint32_t)(wn + bt * 16 + lr) * ROWB + ks * 32 + lc * 16);
#pragma unroll
            for (int mt = 0; mt < 4; mt++)
#pragma unroll
                for (int nt = 0; nt < 8; nt++)
                    MMA_TF32(acc[mt][nt], a[mt], b[nt >> 1][nt & 1], b[nt >> 1][(nt & 1) + 2]);
        }

        if (it == iters - 1) {
            const int m0 = (blockIdx.x + (g / iters) * PGRID) * 128;

            if (!NORM) {
#pragma unroll
                for (int mt = 0; mt < 4; mt++) {
#pragma unroll
                    for (int half = 0; half < 2; half++) {
                        const int m = m0 + wm + mt * 16 + gid + half * 8;
#pragma unroll
                        for (int nt = 0; nt < 8; nt++) {
                            const int n = wn + nt * 8 + t4 * 2;
                            const size_t co = (size_t)m * QD + n;
                            float x0 = acc[mt][nt][half * 2];
                            float x1 = acc[mt][nt][half * 2 + 1];
                            epi_apply<EPI>(x0, n, co, ep);
                            epi_apply<EPI>(x1, n + 1, co + 1, ep);
                            *(float2*)&C[co] = make_float2(x0, x1);
                        }
                    }
                }
            } else {
                // register-resident: apply epi, per-row sumsq via quad shfl + 2KB smem
                float ss[4][2];
#pragma unroll
                for (int mt = 0; mt < 4; mt++) {
#pragma unroll
                    for (int half = 0; half < 2; half++) {
                        const int m = m0 + wm + mt * 16 + gid + half * 8;
                        float s = 0.0f;
#pragma unroll
                        for (int nt = 0; nt < 8; nt++) {
                            const int n = wn + nt * 8 + t4 * 2;
                            const size_t co = (size_t)m * QD + n;
                            epi_apply<EPI>(acc[mt][nt][half * 2], n, co, ep);
                            epi_apply<EPI>(acc[mt][nt][half * 2 + 1], n + 1, co + 1, ep);
                            s += acc[mt][nt][half * 2] * acc[mt][nt][half * 2]
                               + acc[mt][nt][half * 2 + 1] * acc[mt][nt][half * 2 + 1];
                        }
                        s += __shfl_xor_sync(0xffffffffu, s, 1);
                        s += __shfl_xor_sync(0xffffffffu, s, 2);
                        ss[mt][half] = s;   // full 64-col slice sum for this row
                    }
                }
                if (t4 == 0) {
#pragma unroll
                    for (int mt = 0; mt < 4; mt++)
#pragma unroll
                        for (int half = 0; half < 2; half++) {
                            const int rl = wm + mt * 16 + gid + half * 8;
                            s_red[rl * 4 + wcol] = ss[mt][half];
                        }
                }
                __syncthreads();
#pragma unroll
                for (int mt = 0; mt < 4; mt++) {
#pragma unroll
                    for (int half = 0; half < 2; half++) {
                        const int rl = wm + mt * 16 + gid + half * 8;
                        const float tot = s_red[rl * 4] + s_red[rl * 4 + 1]
                                        + s_red[rl * 4 + 2] + s_red[rl * 4 + 3];
                        const float inv = 1.0f / (sqrtf(tot) + 1e-8f);
                        const int m = m0 + rl;
#pragma unroll
                        for (int nt = 0; nt < 8; nt++) {
                            const int n = wn + nt * 8 + t4 * 2;
                            *(float2*)&C[(size_t)m * QD + n] = make_float2(
                                tanh_fast(acc[mt][nt][half * 2] * inv),
                                tanh_fast(acc[mt][nt][half * 2 + 1] * inv));
                        }
                    }
                }
                __syncthreads();   // protect s_red before next tile's epilogue
            }
        }
    }
}

// ---------------- LayerNorm(768) + exact gelu, in place -------------------------
__global__ void ln_gelu_k(float* __restrict__ h,
                          const float* __restrict__ w,
                          const float* __restrict__ b)
{
    const int row = blockIdx.x;
    float* hr = h + (size_t)row * 768;
    const int t = threadIdx.x;

    const float v0 = hr[t], v1 = hr[t + 256], v2 = hr[t + 512];
    float s  = v0 + v1 + v2;
    float ss = v0 * v0 + v1 * v1 + v2 * v2;
#pragma unroll
    for (int o = 16; o > 0; o >>= 1) {
        s  += __shfl_down_sync(0xffffffffu, s, o);
        ss += __shfl_down_sync(0xffffffffu, ss, o);
    }
    __shared__ float rs[8], rss[8], mu_s, rstd_s;
    const int lane = t & 31, wp = t >> 5;
    if (lane == 0) { rs[wp] = s; rss[wp] = ss; }
    __syncthreads();
    if (t == 0) {
        float S = 0.0f, SS = 0.0f;
#pragma unroll
        for (int k = 0; k < 8; k++) { S += rs[k]; SS += rss[k]; }
        const float mu = S * (1.0f / 768.0f);
        mu_s = mu;
        rstd_s = rsqrtf(SS * (1.0f / 768.0f) - mu * mu + 1e-5f);
    }
    __syncthreads();
    const float mu = mu_s, rstd = rstd_s;

#pragma unroll
    for (int k = 0; k < 3; k++) {
        const int c = t + k * 256;
        float x = (((k == 0) ? v0 : (k == 1) ? v1 : v2) - mu) * rstd * w[c] + b[c];
        hr[c] = 0.5f * x * (1.0f + erff(x * 0.70710678118654752f));
    }
}

// ---------------- merged weight transpose + tf32 rounding -----------------------
struct ConvEnt { const float* src; int dstoff; int K; int ldsrc; int coloff; int dotanh; int blk0; };
struct ConvTab { ConvEnt e[32]; int n; };

__global__ void conv_all_k(ConvTab tab, float* __restrict__ dst)
{
    const int blk = blockIdx.x;
    int lo = 0;
    for (int i = 0; i < tab.n; i++)
        if (tab.e[i].blk0 <= blk) lo = i;
    const ConvEnt& E = tab.e[lo];
    const int le = (blk - E.blk0) * 256 + threadIdx.x;
    const int n = le / E.K, k = le - n * E.K;
    float v = E.src[(size_t)k * E.ldsrc + E.coloff + n];
    if (E.dotanh) v = tanhf(v);
    dst[E.dstoff + (size_t)n * E.K + k] = tf32r(v);
}

__global__ void prep_k(const float* __restrict__ gp, float* __restrict__ lin,
                       float* __restrict__ p3, float* __restrict__ p4,
                       float* __restrict__ p5)
{
    const int i = blockIdx.x * 256 + threadIdx.x;
    if (i < 8 * QD) {
        const float* p = gp + (size_t)i * 6;
        lin[i] = sinf(p[0]) + cosf(p[1]) + tanhf(p[2]);
        p3[i] = p[3]; p4[i] = p[4]; p5[i] = p[5];
    }
}

// ---------------- host ----------------------------------------------------------
static void launch_wide(int epi, const float* A, int lda,
                        const float* W, int K, int N,
                        float* C, int ldc, const Epi& ep)
{
    if (epi == E_BIAS)
        gemm_wide<E_BIAS><<<PGRID, 512, SMEM_DYN>>>(A, lda, W, K, C, ldc, K, N, ep);
    else
        gemm_wide<E_SILU><<<PGRID, 512, SMEM_DYN>>>(A, lda, W, K, C, ldc, K, N, ep);
}

template <int EPI, int NORM>
static void launch_n256(const float* A, int lda, const float* W, int K,
                        float* C, const Epi& ep)
{
    gemm_n256<EPI, NORM><<<PGRID, 256, SMEM_DYN>>>(A, lda, W, K, C, K, ep);
}

// tf32 weight-buffer fp32-element offsets
#define W01T 0
#define W02T 589824
#define W11T 1179648
#define W12T 1572864
#define WVT  1966080
#define WOT  2097152
#define TENT 2228224
#define NW1T 2752512
#define NW2T 3014656

extern "C" void kernel_launch(void* const* d_in, const int* in_sizes, int n_in,
                              void* d_out, int out_size)
{
    (void)in_sizes; (void)n_in; (void)out_size;
    const float* x    = (const float*)d_in[0];
    const float* w01  = (const float*)d_in[1];
    const float* b01  = (const float*)d_in[2];
    const float* lnw  = (const float*)d_in[3];
    const float* lnb  = (const float*)d_in[4];
    const float* w02  = (const float*)d_in[5];
    const float* b02  = (const float*)d_in[6];
    const float* w11  = (const float*)d_in[7];
    const float* b11  = (const float*)d_in[8];
    const float* w12  = (const float*)d_in[9];
    const float* b12  = (const float*)d_in[10];
    const float* wqkv = (const float*)d_in[11];
    const float* bqkv = (const float*)d_in[12];
    const float* wo   = (const float*)d_in[13];
    const float* bo   = (const float*)d_in[14];
    const float* gp   = (const float*)d_in[15];
    const float* ent  = (const float*)d_in[16];
    const float* nw1  = (const float*)d_in[17];
    const float* nb1  = (const float*)d_in[18];
    const float* nw2  = (const float*)d_in[19];
    const float* nb2  = (const float*)d_in[20];

    cudaFuncSetAttribute(gemm_wide<E_BIAS>, cudaFuncAttributeMaxDynamicSharedMemorySize, SMEM_DYN);
    cudaFuncSetAttribute(gemm_wide<E_SILU>, cudaFuncAttributeMaxDynamicSharedMemorySize, SMEM_DYN);
    cudaFuncSetAttribute(gemm_n256<E_BIAS, 0>, cudaFuncAttributeMaxDynamicSharedMemorySize, SMEM_DYN);
    cudaFuncSetAttribute(gemm_n256<E_TANH, 0>, cudaFuncAttributeMaxDynamicSharedMemorySize, SMEM_DYN);
    cudaFuncSetAttribute(gemm_n256<E_GATE, 0>, cudaFuncAttributeMaxDynamicSharedMemorySize, SMEM_DYN);
    cudaFuncSetAttribute(gemm_n256<E_GATE, 1>, cudaFuncAttributeMaxDynamicSharedMemorySize, SMEM_DYN);
    cudaFuncSetAttribute(gemm_n256<E_NL, 1>,   cudaFuncAttributeMaxDynamicSharedMemorySize, SMEM_DYN);

    float *H, *FB, *GATEB, *WT;
    cudaGetSymbolAddress((void**)&H,     g_h);
    cudaGetSymbolAddress((void**)&FB,    g_f);
    cudaGetSymbolAddress((void**)&WT,    g_wtf);
    cudaGetSymbolAddress((void**)&GATEB, g_gate);

    float* F[3];
    for (int k = 0; k < 3; k++) F[k] = FB + (size_t)k * BATCH_N * QD;
    float* LIN = GATEB + 0 * 8 * QD;
    float* P3  = GATEB + 1 * 8 * QD;
    float* P4  = GATEB + 2 * 8 * QD;
    float* P5  = GATEB + 3 * 8 * QD;

    // ---- merged one-time weight transpose/round ----
    {
        ConvTab tab; int ne = 0, blk = 0;
        auto add = [&](const float* src, size_t zs, int ldsrc, int coloff,
                       int dstoff, size_t dzs, int K, int N, int th, int zn) {
            for (int z = 0; z < zn; z++) {
                tab.e[ne] = { src + (size_t)z * zs, (int)(dstoff + (size_t)z * dzs),
                              K, ldsrc, coloff, th, blk };
                blk += (K * N) / 256;
                ne++;
            }
        };
        add(w01, (size_t)QD * 768, 768, 0,   W01T, 196608, QD, 768, 0, 3);
        add(w02, (size_t)768 * QD, QD,  0,   W02T, 196608, 768, QD, 0, 3);
        add(w11, (size_t)QD * 512, 512, 0,   W11T, 131072, QD, 512, 0, 3);
        add(w12, (size_t)512 * QD, QD,  0,   W12T, 131072, 512, QD, 0, 3);
        add(wqkv, (size_t)QD * 768, 768, 512, WVT, 65536, QD, QD, 0, 2);
        add(wo,  (size_t)QD * QD,  QD,  0,   WOT,  65536, QD, QD, 0, 2);
        add(ent, (size_t)QD * QD,  QD,  0,   TENT, 65536, QD, QD, 1, 8);
        add(nw1, (size_t)QD * QD,  QD,  0,   NW1T, 65536, QD, QD, 0, 4);
        add(nw2, (size_t)QD * QD,  QD,  0,   NW2T, 65536, QD, QD, 0, 4);
        tab.n = ne;
        conv_all_k<<<blk, 256>>>(tab, WT);
    }
    prep_k<<<8, 256>>>(gp, LIN, P3, P4, P5);

    const float* cur = x;
    int scur = -1;

    for (int li = 0; li < 8; li++) {
        int s0 = -1, s1 = -1;
        for (int k = 0; k < 3; k++)
            if (k != scur) { if (s0 < 0) s0 = k; else if (s1 < 0) s1 = k; }
        float* F0 = F[s0]; float* F1 = F[s1];

        const int t = li % 3;
        const int odd = li & 1;
        const float alpha = (li < 4) ? 0.8f : 0.6f;

        if (t == 0) {
            const int i = li / 3;
            Epi e = {}; e.bias = b01 + i * 768;
            launch_wide(E_BIAS, cur, QD, WT + W01T + (size_t)i * 196608, QD, 768, H, 768, e);
            ln_gelu_k<<<BATCH_N, 256>>>(H, lnw + i * 768, lnb + i * 768);
            Epi e2 = {}; e2.bias = b02 + i * QD;
            launch_n256<E_BIAS, 0>(H, 768, WT + W02T + (size_t)i * 196608, 768, F0, e2);
        } else if (t == 1) {
            const int i = (li - 1) / 3;
            Epi e = {}; e.bias = b11 + i * 512;
            launch_wide(E_SILU, cur, QD, WT + W11T + (size_t)i * 131072, QD, 512, H, 512, e);
            Epi e2 = {}; e2.bias = b12 + i * QD;
            launch_n256<E_BIAS, 0>(H, 512, WT + W12T + (size_t)i * 131072, 512, F0, e2);
        } else {
            const int i = (li - 2) / 3;
            Epi e = {}; e.bias = bqkv + i * 768 + 512;
            launch_n256<E_BIAS, 0>(cur, QD, WT + WVT + (size_t)i * 65536, QD, F1, e);
            Epi e2 = {}; e2.bias = bo + i * QD;
            launch_n256<E_BIAS, 0>(F1, QD, WT + WOT + (size_t)i * 65536, QD, F0, e2);
        }

        // entangle + gate; even layers also blend + row-norm + tanh (final for layer)
        Epi eg = {};
        eg.cmat = F0; eg.resmat = cur;
        eg.lin = LIN + li * QD; eg.p3 = P3 + li * QD;
        eg.p4 = P4 + li * QD;   eg.p5 = P5 + li * QD;
        eg.alpha = alpha; eg.blend = !odd;
        if (!odd) {
            launch_n256<E_GATE, 1>(F0, QD, WT + TENT + (size_t)li * 65536, QD, F1, eg);
            cur = F1; scur = s1;
        } else {
            launch_n256<E_GATE, 0>(F0, QD, WT + TENT + (size_t)li * 65536, QD, F1, eg);
            const int j = li / 2;
            Epi et = {}; et.bias = nb1 + j * QD;
            launch_n256<E_TANH, 0>(F1, QD, WT + NW1T + (size_t)j * 65536, QD, H, et);
            Epi en = {}; en.bias = nb2 + j * QD;
            en.cmat = F1; en.resmat = cur; en.alpha = alpha;
            float* dst = (li == 7) ? (float*)d_out : F1;
            launch_n256<E_NL, 1>(H, QD, WT + NW2T + (size_t)j * 65536, QD, dst, en);
            cur = dst; scur = s1;
        }
    }
}

// round 10
// speedup vs baseline: 1.0596x; 1.0596x over previous
#include <cuda_runtime.h>
#include <cuda_bf16.h>
#include <math.h>
#include <stdint.h>
#include <stddef.h>

#define BATCH_N 65536
#define QD      256

// ---------------- ptx helpers ---------------------------------------------------
__device__ __forceinline__ uint32_t smem_u32(const void* p) {
    uint32_t a;
    asm("{ .reg .u64 t; cvta.to.shared.u64 t, %1; cvt.u32.u64 %0, t; }" : "=r"(a) : "l"(p));
    return a;
}

#define CP_ASYNC16(dst, src) \
    asm volatile("cp.async.cg.shared.global [%0], [%1], 16;" :: "r"(dst), "l"(src) : "memory")
#define CP_COMMIT() asm volatile("cp.async.commit_group;" ::: "memory")
#define CP_WAIT1()  asm volatile("cp.async.wait_group 1;" ::: "memory")
#define CP_WAIT0()  asm volatile("cp.async.wait_group 0;" ::: "memory")

#define LDSM_X4(r, addr) \
    asm volatile("ldmatrix.sync.aligned.m8n8.x4.shared.b16 {%0,%1,%2,%3}, [%4];" \
        : "=r"((r)[0]), "=r"((r)[1]), "=r"((r)[2]), "=r"((r)[3]) : "r"(addr))

#define MMA_TF32(c, a, b0, b1) \
    asm volatile("mma.sync.aligned.m16n8k8.row.col.f32.tf32.tf32.f32 " \
        "{%0,%1,%2,%3}, {%4,%5,%6,%7}, {%8,%9}, {%0,%1,%2,%3};" \
        : "+f"((c)[0]), "+f"((c)[1]), "+f"((c)[2]), "+f"((c)[3]) \
        : "r"((a)[0]), "r"((a)[1]), "r"((a)[2]), "r"((a)[3]), "r"(b0), "r"(b1))

#define CVT_TF32(r) asm volatile("cvt.rna.tf32.f32 %0, %0;" : "+r"(r))

__device__ __forceinline__ float tf32r(float v) {
    asm("cvt.rna.tf32.f32 %0, %0;" : "+f"(v));
    return v;
}

__device__ __forceinline__ float tanh_fast(float x) {
    return 1.0f - 2.0f / (__expf(2.0f * x) + 1.0f);
}

// ---------------- scratch -------------------------------------------------------
static __device__ __align__(16) float g_h[(size_t)BATCH_N * 768];
static __device__ __align__(16) float g_f[3][(size_t)BATCH_N * QD];
static __device__ __align__(16) float g_wtf[3276800];
static __device__ __align__(16) float g_gate[4][8 * QD];
static __device__ __align__(16) float g_bcmb[2 * QD];

struct Epi {
    const float* bias;
    const float* cmat;
    const float* resmat;
    const float* lin; const float* p3; const float* p4; const float* p5;
    float alpha;
    int   blend;
};

enum { E_BIAS = 0, E_SILU = 1, E_TANH = 2, E_GATE = 3, E_NL = 4 };

#define ROWB 144                       // 128B data + 16B skew

template <int EPI>
__device__ __forceinline__ void epi_apply(float& x, int n, size_t co, const Epi& ep) {
    if (EPI == E_BIAS) {
        x += ep.bias[n];
    } else if (EPI == E_SILU) {
        x += ep.bias[n];
        x = x / (1.0f + __expf(-x));
    } else if (EPI == E_TANH) {
        x += ep.bias[n];
        x = tanh_fast(x);
    } else if (EPI == E_GATE) {
        const float c = ep.cmat[co];
        const float g = (ep.lin[n] * c
                         + 0.5f * __sinf(ep.p3[n] * c + ep.p4[n])
                         + 0.5f * __cosf(ep.p5[n] * c)) * 0.25f;
        x = (c + 0.3f * g + 0.2f * x) * (1.0f / 1.5f);
        if (ep.blend)
            x = ep.alpha * x + (1.0f - ep.alpha) * ep.resmat[co];
    } else if (EPI == E_NL) {
        x += ep.bias[n];
        const float c2 = ep.cmat[co];
        x = ep.alpha * (c2 + 0.1f * x) + (1.0f - ep.alpha) * ep.resmat[co];
    }
}

// ============ wide GEMM: CTA 256x128, 512 thr, warp 64x32 (N=768/512) ===========
#define OP_A  (256 * ROWB)
#define OP_Bw (128 * ROWB)
#define STGW  (OP_A + OP_Bw)
#define NSTG  3
#define SMEM_DYN (NSTG * STGW)         // 165888

template <int EPI>
__global__ void __launch_bounds__(512, 1) gemm_wide(
    const float* __restrict__ A, int lda,
    const float* __restrict__ W, int ldb,
    float* __restrict__ C, int ldc, int K, Epi ep)
{
    extern __shared__ __align__(16) char dyns[];
    const uint32_t sbase = smem_u32(dyns);

    const int tid  = threadIdx.x;
    const int wid  = tid >> 5, lane = tid & 31;
    const int m0   = blockIdx.y * 256;
    const int n0   = blockIdx.x * 128;
    const int wm   = (wid >> 2) * 64;
    const int wn   = (wid & 3) * 32;

    const int iters = K / 32;

    const int crow = tid >> 3;
    const int ccol = (tid & 7) * 16;
    const int gcol = (tid & 7) * 4;

    auto load_stage = [&](int s, int it) {
        const int ko = it * 32;
        const uint32_t smA = sbase + (uint32_t)s * STGW;
        const uint32_t smB = smA + OP_A;
        const float* ga = A + (size_t)(m0 + crow) * lda + ko + gcol;
        const float* gb = W + (size_t)(n0 + crow) * ldb + ko + gcol;
#pragma unroll
        for (int i = 0; i < 4; i++)
            CP_ASYNC16(smA + (uint32_t)(crow + i * 64) * ROWB + ccol, ga + (size_t)(i * 64) * lda);
#pragma unroll
        for (int i = 0; i < 2; i++)
            CP_ASYNC16(smB + (uint32_t)(crow + i * 64) * ROWB + ccol, gb + (size_t)(i * 64) * ldb);
        CP_COMMIT();
    };

    float acc[4][4][4];
#pragma unroll
    for (int i = 0; i < 4; i++)
#pragma unroll
        for (int j = 0; j < 4; j++)
#pragma unroll
            for (int q = 0; q < 4; q++) acc[i][j][q] = 0.0f;

    load_stage(0, 0);
    load_stage(1, 1);

    const int lr = lane & 15, lc = lane >> 4;

    for (int it = 0; it < iters; ++it) {
        if (it == iters - 1) { CP_WAIT0(); } else { CP_WAIT1(); }
        __syncthreads();
        if (it + 2 < iters) load_stage((it + 2) % NSTG, it + 2);

        const uint32_t smA = sbase + (uint32_t)(it % NSTG) * STGW;
        const uint32_t smB = smA + OP_A;

#pragma unroll
        for (int ks = 0; ks < 4; ks++) {
            uint32_t a[4][4], b[2][4];
#pragma unroll
            for (int mt = 0; mt < 4; mt++) {
                LDSM_X4(a[mt], smA + (uint32_t)(wm + mt * 16 + lr) * ROWB + ks * 32 + lc * 16);
#pragma unroll
                for (int q = 0; q < 4; q++) CVT_TF32(a[mt][q]);
            }
#pragma unroll
            for (int bt = 0; bt < 2; bt++)
                LDSM_X4(b[bt], smB + (uint32_t)(wn + bt * 16 + lr) * ROWB + ks * 32 + lc * 16);
#pragma unroll
            for (int mt = 0; mt < 4; mt++)
#pragma unroll
                for (int nt = 0; nt < 4; nt++)
                    MMA_TF32(acc[mt][nt], a[mt], b[nt >> 1][nt & 1], b[nt >> 1][(nt & 1) + 2]);
        }
    }

    const int gid = lane >> 2, t4 = lane & 3;
#pragma unroll
    for (int mt = 0; mt < 4; mt++) {
#pragma unroll
        for (int half = 0; half < 2; half++) {
            const int m = m0 + wm + mt * 16 + gid + half * 8;
#pragma unroll
            for (int nt = 0; nt < 4; nt++) {
                const int n = n0 + wn + nt * 8 + t4 * 2;
                const size_t co = (size_t)m * ldc + n;
                float x0 = acc[mt][nt][half * 2];
                float x1 = acc[mt][nt][half * 2 + 1];
                epi_apply<EPI>(x0, n, co, ep);
                epi_apply<EPI>(x1, n + 1, co + 1, ep);
                *(float2*)&C[co] = make_float2(x0, x1);
            }
        }
    }
}

// ============ n256 GEMM: CTA 128x256, 256 thr, warp 64x64, optional row-norm ====
#define OP_An (128 * ROWB)
#define OP_Bn (256 * ROWB)
#define STGN  (OP_An + OP_Bn)          // 55296 -> 3* = 165888
#define SV_STRIDE 260

template <int EPI, int NORM>
__global__ void __launch_bounds__(256, 1) gemm_n256(
    const float* __restrict__ A, int lda,
    const float* __restrict__ W, int ldb,
    float* __restrict__ C, int K, Epi ep)
{
    extern __shared__ __align__(16) char dyns[];
    const uint32_t sbase = smem_u32(dyns);

    const int tid  = threadIdx.x;
    const int wid  = tid >> 5, lane = tid & 31;
    const int m0   = blockIdx.x * 128;
    const int wm   = (wid >> 2) * 64;      // 0 / 64
    const int wn   = (wid & 3) * 64;       // 0..192

    const int iters = K / 32;

    const int crow = tid >> 3;             // 0..31
    const int ccol = (tid & 7) * 16;
    const int gcol = (tid & 7) * 4;

    auto load_stage = [&](int s, int it) {
        const int ko = it * 32;
        const uint32_t smA = sbase + (uint32_t)s * STGN;
        const uint32_t smB = smA + OP_An;
        const float* ga = A + (size_t)(m0 + crow) * lda + ko + gcol;
        const float* gb = W + (size_t)crow * ldb + ko + gcol;
#pragma unroll
        for (int i = 0; i < 4; i++)
            CP_ASYNC16(smA + (uint32_t)(crow + i * 32) * ROWB + ccol, ga + (size_t)(i * 32) * lda);
#pragma unroll
        for (int i = 0; i < 8; i++)
            CP_ASYNC16(smB + (uint32_t)(crow + i * 32) * ROWB + ccol, gb + (size_t)(i * 32) * ldb);
        CP_COMMIT();
    };

    float acc[4][8][4];
#pragma unroll
    for (int i = 0; i < 4; i++)
#pragma unroll
        for (int j = 0; j < 8; j++)
#pragma unroll
            for (int q = 0; q < 4; q++) acc[i][j][q] = 0.0f;

    load_stage(0, 0);
    load_stage(1, 1);

    const int lr = lane & 15, lc = lane >> 4;

    for (int it = 0; it < iters; ++it) {
        if (it == iters - 1) { CP_WAIT0(); } else { CP_WAIT1(); }
        __syncthreads();
        if (it + 2 < iters) load_stage((it + 2) % NSTG, it + 2);

        const uint32_t smA = sbase + (uint32_t)(it % NSTG) * STGN;
        const uint32_t smB = smA + OP_An;

#pragma unroll
        for (int ks = 0; ks < 4; ks++) {
            uint32_t a[4][4], b[4][4];
#pragma unroll
            for (int mt = 0; mt < 4; mt++) {
                LDSM_X4(a[mt], smA + (uint32_t)(wm + mt * 16 + lr) * ROWB + ks * 32 + lc * 16);
#pragma unroll
                for (int q = 0; q < 4; q++) CVT_TF32(a[mt][q]);
            }
#pragma unroll
            for (int bt = 0; bt < 4; bt++)
                LDSM_X4(b[bt], smB + (uint32_t)(wn + bt * 16 + lr) * ROWB + ks * 32 + lc * 16);
#pragma unroll
            for (int mt = 0; mt < 4; mt++)
#pragma unroll
                for (int nt = 0; nt < 8; nt++)
                    MMA_TF32(acc[mt][nt], a[mt], b[nt >> 1][nt & 1], b[nt >> 1][(nt & 1) + 2]);
        }
    }

    const int gid = lane >> 2, t4 = lane & 3;

    if (!NORM) {
#pragma unroll
        for (int mt = 0; mt < 4; mt++) {
#pragma unroll
            for (int half = 0; half < 2; half++) {
                const int m = m0 + wm + mt * 16 + gid + half * 8;
#pragma unroll
                for (int nt = 0; nt < 8; nt++) {
                    const int n = wn + nt * 8 + t4 * 2;
                    const size_t co = (size_t)m * QD + n;
                    float x0 = acc[mt][nt][half * 2];
                    float x1 = acc[mt][nt][half * 2 + 1];
                    epi_apply<EPI>(x0, n, co, ep);
                    epi_apply<EPI>(x1, n + 1, co + 1, ep);
                    *(float2*)&C[co] = make_float2(x0, x1);
                }
            }
        }
    } else {
        // stage epi-applied values into (now dead) pipeline smem, row-norm, tanh
        float* sv = (float*)dyns;
        __syncthreads();   // all ldmatrix reads done before overwrite
#pragma unroll
        for (int mt = 0; mt < 4; mt++) {
#pragma unroll
            for (int half = 0; half < 2; half++) {
                const int ml = wm + mt * 16 + gid + half * 8;   // 0..127 local row
                const int m  = m0 + ml;
#pragma unroll
                for (int nt = 0; nt < 8; nt++) {
                    const int n = wn + nt * 8 + t4 * 2;
                    const size_t co = (size_t)m * QD + n;
                    float x0 = acc[mt][nt][half * 2];
                    float x1 = acc[mt][nt][half * 2 + 1];
                    epi_apply<EPI>(x0, n, co, ep);
                    epi_apply<EPI>(x1, n + 1, co + 1, ep);
                    *(float2*)&sv[ml * SV_STRIDE + n] = make_float2(x0, x1);
                }
            }
        }
        __syncthreads();
        if (tid < 128) {
            const float* r = &sv[tid * SV_STRIDE];
            float s = 0.0f;
#pragma unroll 16
            for (int c = 0; c < 256; c += 4) {
                const float4 v = *(const float4*)&r[c];
                s += v.x * v.x + v.y * v.y + v.z * v.z + v.w * v.w;
            }
            sv[tid * SV_STRIDE + 256] = 1.0f / (sqrtf(s) + 1e-8f);
        }
        __syncthreads();
#pragma unroll 1
        for (int i = 0; i < 32; i++) {
            const int idx = i * 1024 + tid * 4;
            const int row = idx >> 8, col = idx & 255;
            const float inv = sv[row * SV_STRIDE + 256];
            const float4 v = *(const float4*)&sv[row * SV_STRIDE + col];
            *(float4*)&C[(size_t)(m0 + row) * QD + col] =
                make_float4(tanh_fast(v.x * inv), tanh_fast(v.y * inv),
                            tanh_fast(v.z * inv), tanh_fast(v.w * inv));
        }
    }
}

// ---------------- LayerNorm(768) + exact gelu, in place -------------------------
__global__ void ln_gelu_k(float* __restrict__ h,
                          const float* __restrict__ w,
                          const float* __restrict__ b)
{
    const int row = blockIdx.x;
    float* hr = h + (size_t)row * 768;
    const int t = threadIdx.x;

    const float v0 = hr[t], v1 = hr[t + 256], v2 = hr[t + 512];
    float s  = v0 + v1 + v2;
    float ss = v0 * v0 + v1 * v1 + v2 * v2;
#pragma unroll
    for (int o = 16; o > 0; o >>= 1) {
        s  += __shfl_down_sync(0xffffffffu, s, o);
        ss += __shfl_down_sync(0xffffffffu, ss, o);
    }
    __shared__ float rs[8], rss[8], mu_s, rstd_s;
    const int lane = t & 31, wp = t >> 5;
    if (lane == 0) { rs[wp] = s; rss[wp] = ss; }
    __syncthreads();
    if (t == 0) {
        float S = 0.0f, SS = 0.0f;
#pragma unroll
        for (int k = 0; k < 8; k++) { S += rs[k]; SS += rss[k]; }
        const float mu = S * (1.0f / 768.0f);
        mu_s = mu;
        rstd_s = rsqrtf(SS * (1.0f / 768.0f) - mu * mu + 1e-5f);
    }
    __syncthreads();
    const float mu = mu_s, rstd = rstd_s;

#pragma unroll
    for (int k = 0; k < 3; k++) {
        const int c = t + k * 256;
        float x = (((k == 0) ? v0 : (k == 1) ? v1 : v2) - mu) * rstd * w[c] + b[c];
        hr[c] = 0.5f * x * (1.0f + erff(x * 0.70710678118654752f));
    }
}

// ---------------- merged weight transpose + tf32 rounding -----------------------
struct ConvEnt { const float* src; int dstoff; int K; int ldsrc; int coloff; int dotanh; int blk0; };
struct ConvTab { ConvEnt e[32]; int n; };

__global__ void conv_all_k(ConvTab tab, float* __restrict__ dst)
{
    const int blk = blockIdx.x;
    int lo = 0;
    for (int i = 0; i < tab.n; i++)
        if (tab.e[i].blk0 <= blk) lo = i;
    const ConvEnt& E = tab.e[lo];
    const int le = (blk - E.blk0) * 256 + threadIdx.x;
    const int n = le / E.K, k = le - n * E.K;
    float v = E.src[(size_t)k * E.ldsrc + E.coloff + n];
    if (E.dotanh) v = tanhf(v);
    dst[E.dstoff + (size_t)n * E.K + k] = tf32r(v);
}

// ---------------- combined attention weight: Wcomb = Wv @ Wo --------------------
// dst[n*256+k] = sum_j wqkv[k,512+j] * wo[j,n]  (transposed [N,K] storage, tf32)
// bcmb[n] = sum_j bqkv[512+j] * wo[j,n] + bo[n]
__global__ void comb_k(const float* __restrict__ wqkv, const float* __restrict__ bqkv,
                       const float* __restrict__ wo, const float* __restrict__ bo,
                       float* __restrict__ dst, float* __restrict__ bcmb)
{
    const int i = blockIdx.y;         // matrix index 0/1
    const int n = blockIdx.x;         // 0..255
    const int k = threadIdx.x;        // 0..255
    __shared__ float swo[256];
    swo[k] = wo[(size_t)i * 65536 + (size_t)k * 256 + n];
    __syncthreads();
    const float* wv = wqkv + (size_t)i * 196608 + (size_t)k * 768 + 512;
    float s = 0.0f;
#pragma unroll 8
    for (int j = 0; j < 256; j++) s += wv[j] * swo[j];
    dst[(size_t)i * 65536 + (size_t)n * 256 + k] = tf32r(s);
    if (k == 0) {
        float b = 0.0f;
        const float* bv = bqkv + (size_t)i * 768 + 512;
        for (int j = 0; j < 256; j++) b += bv[j] * swo[j];
        bcmb[i * 256 + n] = b + bo[i * 256 + n];
    }
}

__global__ void prep_k(const float* __restrict__ gp, float* __restrict__ lin,
                       float* __restrict__ p3, float* __restrict__ p4,
                       float* __restrict__ p5)
{
    const int i = blockIdx.x * 256 + threadIdx.x;
    if (i < 8 * QD) {
        const float* p = gp + (size_t)i * 6;
        lin[i] = sinf(p[0]) + cosf(p[1]) + tanhf(p[2]);
        p3[i] = p[3]; p4[i] = p[4]; p5[i] = p[5];
    }
}

// ---------------- host ----------------------------------------------------------
static void launch_wide(int epi, const float* A, int lda,
                        const float* W, int K, int N,
                        float* C, int ldc, const Epi& ep)
{
    dim3 grid(N / 128, BATCH_N / 256);
    dim3 blk(512);
    if (epi == E_BIAS) gemm_wide<E_BIAS><<<grid, blk, SMEM_DYN>>>(A, lda, W, K, C, ldc, K, ep);
    else               gemm_wide<E_SILU><<<grid, blk, SMEM_DYN>>>(A, lda, W, K, C, ldc, K, ep);
}

template <int EPI, int NORM>
static void launch_n256(const float* A, int lda, const float* W, int K,
                        float* C, const Epi& ep)
{
    gemm_n256<EPI, NORM><<<BATCH_N / 128, 256, SMEM_DYN>>>(A, lda, W, K, C, K, ep);
}

// tf32 weight-buffer fp32-element offsets
#define W01T 0
#define W02T 589824
#define W11T 1179648
#define W12T 1572864
#define WCMB 1966080
#define TENT 2228224
#define NW1T 2752512
#define NW2T 3014656

extern "C" void kernel_launch(void* const* d_in, const int* in_sizes, int n_in,
                              void* d_out, int out_size)
{
    (void)in_sizes; (void)n_in; (void)out_size;
    const float* x    = (const float*)d_in[0];
    const float* w01  = (const float*)d_in[1];
    const float* b01  = (const float*)d_in[2];
    const float* lnw  = (const float*)d_in[3];
    const float* lnb  = (const float*)d_in[4];
    const float* w02  = (const float*)d_in[5];
    const float* b02  = (const float*)d_in[6];
    const float* w11  = (const float*)d_in[7];
    const float* b11  = (const float*)d_in[8];
    const float* w12  = (const float*)d_in[9];
    const float* b12  = (const float*)d_in[10];
    const float* wqkv = (const float*)d_in[11];
    const float* bqkv = (const float*)d_in[12];
    const float* wo   = (const float*)d_in[13];
    const float* bo   = (const float*)d_in[14];
    const float* gp   = (const float*)d_in[15];
    const float* ent  = (const float*)d_in[16];
    const float* nw1  = (const float*)d_in[17];
    const float* nb1  = (const float*)d_in[18];
    const float* nw2  = (const float*)d_in[19];
    const float* nb2  = (const float*)d_in[20];

    cudaFuncSetAttribute(gemm_wide<E_BIAS>, cudaFuncAttributeMaxDynamicSharedMemorySize, SMEM_DYN);
    cudaFuncSetAttribute(gemm_wide<E_SILU>, cudaFuncAttributeMaxDynamicSharedMemorySize, SMEM_DYN);
    cudaFuncSetAttribute(gemm_n256<E_BIAS, 0>, cudaFuncAttributeMaxDynamicSharedMemorySize, SMEM_DYN);
    cudaFuncSetAttribute(gemm_n256<E_TANH, 0>, cudaFuncAttributeMaxDynamicSharedMemorySize, SMEM_DYN);
    cudaFuncSetAttribute(gemm_n256<E_GATE, 0>, cudaFuncAttributeMaxDynamicSharedMemorySize, SMEM_DYN);
    cudaFuncSetAttribute(gemm_n256<E_GATE, 1>, cudaFuncAttributeMaxDynamicSharedMemorySize, SMEM_DYN);
    cudaFuncSetAttribute(gemm_n256<E_NL, 1>,   cudaFuncAttributeMaxDynamicSharedMemorySize, SMEM_DYN);

    float *H, *FB, *GATEB, *WT, *BCMB;
    cudaGetSymbolAddress((void**)&H,     g_h);
    cudaGetSymbolAddress((void**)&FB,    g_f);
    cudaGetSymbolAddress((void**)&WT,    g_wtf);
    cudaGetSymbolAddress((void**)&GATEB, g_gate);
    cudaGetSymbolAddress((void**)&BCMB,  g_bcmb);

    float* F[3];
    for (int k = 0; k < 3; k++) F[k] = FB + (size_t)k * BATCH_N * QD;
    float* LIN = GATEB + 0 * 8 * QD;
    float* P3  = GATEB + 1 * 8 * QD;
    float* P4  = GATEB + 2 * 8 * QD;
    float* P5  = GATEB + 3 * 8 * QD;

    // ---- merged one-time weight transpose/round ----
    {
        ConvTab tab; int ne = 0, blk = 0;
        auto add = [&](const float* src, size_t zs, int ldsrc, int coloff,
                       int dstoff, size_t dzs, int K, int N, int th, int zn) {
            for (int z = 0; z < zn; z++) {
                tab.e[ne] = { src + (size_t)z * zs, (int)(dstoff + (size_t)z * dzs),
                              K, ldsrc, coloff, th, blk };
                blk += (K * N) / 256;
                ne++;
            }
        };
        add(w01, (size_t)QD * 768, 768, 0,   W01T, 196608, QD, 768, 0, 3);
        add(w02, (size_t)768 * QD, QD,  0,   W02T, 196608, 768, QD, 0, 3);
        add(w11, (size_t)QD * 512, 512, 0,   W11T, 131072, QD, 512, 0, 3);
        add(w12, (size_t)512 * QD, QD,  0,   W12T, 131072, 512, QD, 0, 3);
        add(ent, (size_t)QD * QD,  QD,  0,   TENT, 65536, QD, QD, 1, 8);
        add(nw1, (size_t)QD * QD,  QD,  0,   NW1T, 65536, QD, QD, 0, 4);
        add(nw2, (size_t)QD * QD,  QD,  0,   NW2T, 65536, QD, QD, 0, 4);
        tab.n = ne;
        conv_all_k<<<blk, 256>>>(tab, WT);
    }
    comb_k<<<dim3(256, 2), 256>>>(wqkv, bqkv, wo, bo, WT + WCMB, BCMB);
    prep_k<<<8, 256>>>(gp, LIN, P3, P4, P5);

    const float* cur = x;
    int scur = -1;

    for (int li = 0; li < 8; li++) {
        int s0 = -1, s1 = -1;
        for (int k = 0; k < 3; k++)
            if (k != scur) { if (s0 < 0) s0 = k; else if (s1 < 0) s1 = k; }
        float* F0 = F[s0]; float* F1 = F[s1];

        const int t = li % 3;
        const int odd = li & 1;
        const float alpha = (li < 4) ? 0.8f : 0.6f;

        if (t == 0) {
            const int i = li / 3;
            Epi e = {}; e.bias = b01 + i * 768;
            launch_wide(E_BIAS, cur, QD, WT + W01T + (size_t)i * 196608, QD, 768, H, 768, e);
            ln_gelu_k<<<BATCH_N, 256>>>(H, lnw + i * 768, lnb + i * 768);
            Epi e2 = {}; e2.bias = b02 + i * QD;
            launch_n256<E_BIAS, 0>(H, 768, WT + W02T + (size_t)i * 196608, 768, F0, e2);
        } else if (t == 1) {
            const int i = (li - 1) / 3;
            Epi e = {}; e.bias = b11 + i * 512;
            launch_wide(E_SILU, cur, QD, WT + W11T + (size_t)i * 131072, QD, 512, H, 512, e);
            Epi e2 = {}; e2.bias = b12 + i * QD;
            launch_n256<E_BIAS, 0>(H, 512, WT + W12T + (size_t)i * 131072, 512, F0, e2);
        } else {
            // attention layer collapsed: cur @ (Wv@Wo) + (bv@Wo + bo)
            const int i = (li - 2) / 3;
            Epi e = {}; e.bias = BCMB + i * QD;
            launch_n256<E_BIAS, 0>(cur, QD, WT + WCMB + (size_t)i * 65536, QD, F0, e);
        }

        // entangle + gate; even layers also blend + row-norm + tanh (final for layer)
        Epi eg = {};
        eg.cmat = F0; eg.resmat = cur;
        eg.lin = LIN + li * QD; eg.p3 = P3 + li * QD;
        eg.p4 = P4 + li * QD;   eg.p5 = P5 + li * QD;
        eg.alpha = alpha; eg.blend = !odd;
        if (!odd) {
            launch_n256<E_GATE, 1>(F0, QD, WT + TENT + (size_t)li * 65536, QD, F1, eg);
            cur = F1; scur = s1;
        } else {
            launch_n256<E_GATE, 0>(F0, QD, WT + TENT + (size_t)li * 65536, QD, F1, eg);
            const int j = li / 2;
            Epi et = {}; et.bias = nb1 + j * QD;
            launch_n256<E_TANH, 0>(F1, QD, WT + NW1T + (size_t)j * 65536, QD, H, et);
            Epi en = {}; en.bias = nb2 + j * QD;
            en.cmat = F1; en.resmat = cur; en.alpha = alpha;
            float* dst = (li == 7) ? (float*)d_out : F1;
            launch_n256<E_NL, 1>(H, QD, WT + NW2T + (size_t)j * 65536, QD, dst, en);
            cur = dst; scur = s1;
        }
    }
}

// round 12
// speedup vs baseline: 1.1764x; 1.1102x over previous
#include <cuda_runtime.h>
#include <cuda_bf16.h>
#include <math.h>
#include <stdint.h>
#include <stddef.h>

#define BATCH_N 65536
#define QD      256

// ---------------- ptx helpers ---------------------------------------------------
__device__ __forceinline__ uint32_t smem_u32(const void* p) {
    uint32_t a;
    asm("{ .reg .u64 t; cvta.to.shared.u64 t, %1; cvt.u32.u64 %0, t; }" : "=r"(a) : "l"(p));
    return a;
}

#define CP_ASYNC16(dst, src) \
    asm volatile("cp.async.cg.shared.global [%0], [%1], 16;" :: "r"(dst), "l"(src) : "memory")
#define CP_COMMIT() asm volatile("cp.async.commit_group;" ::: "memory")
#define CP_WAIT1()  asm volatile("cp.async.wait_group 1;" ::: "memory")
#define CP_WAIT0()  asm volatile("cp.async.wait_group 0;" ::: "memory")

#define LDSM_X4(r, addr) \
    asm volatile("ldmatrix.sync.aligned.m8n8.x4.shared.b16 {%0,%1,%2,%3}, [%4];" \
        : "=r"((r)[0]), "=r"((r)[1]), "=r"((r)[2]), "=r"((r)[3]) : "r"(addr))

#define MMA_TF32(c, a, b0, b1) \
    asm volatile("mma.sync.aligned.m16n8k8.row.col.f32.tf32.tf32.f32 " \
        "{%0,%1,%2,%3}, {%4,%5,%6,%7}, {%8,%9}, {%0,%1,%2,%3};" \
        : "+f"((c)[0]), "+f"((c)[1]), "+f"((c)[2]), "+f"((c)[3]) \
        : "r"((a)[0]), "r"((a)[1]), "r"((a)[2]), "r"((a)[3]), "r"(b0), "r"(b1))

#define CVT_TF32(r) asm volatile("cvt.rna.tf32.f32 %0, %0;" : "+r"(r))

__device__ __forceinline__ float tf32r(float v) {
    asm("cvt.rna.tf32.f32 %0, %0;" : "+f"(v));
    return v;
}

__device__ __forceinline__ float tanh_fast(float x) {
    return 1.0f - 2.0f / (__expf(2.0f * x) + 1.0f);
}

// ---------------- scratch -------------------------------------------------------
static __device__ __align__(16) float g_h[(size_t)BATCH_N * 768];
static __device__ __align__(16) float g_f[3][(size_t)BATCH_N * QD];
static __device__ __align__(16) float g_wtf[3276800];
static __device__ __align__(16) float g_gate[4][8 * QD];
static __device__ __align__(16) float g_bcmb[2 * QD];

struct Epi {
    const float* bias;
    const float* cmat;
    const float* resmat;
    const float* lin; const float* p3; const float* p4; const float* p5;
    float alpha;
    int   blend;
};

enum { E_BIAS = 0, E_SILU = 1, E_TANH = 2, E_GATE = 3, E_NL = 4 };

#define ROWB 144                       // 128B data + 16B skew
#define NSTG 3

template <int EPI>
__device__ __forceinline__ void epi_apply(float& x, int n, size_t co, const Epi& ep) {
    if (EPI == E_BIAS) {
        x += ep.bias[n];
    } else if (EPI == E_SILU) {
        x += ep.bias[n];
        x = x / (1.0f + __expf(-x));
    } else if (EPI == E_TANH) {
        x += ep.bias[n];
        x = tanh_fast(x);
    } else if (EPI == E_GATE) {
        const float c = ep.cmat[co];
        const float g = (ep.lin[n] * c
                         + 0.5f * __sinf(ep.p3[n] * c + ep.p4[n])
                         + 0.5f * __cosf(ep.p5[n] * c)) * 0.25f;
        x = (c + 0.3f * g + 0.2f * x) * (1.0f / 1.5f);
        if (ep.blend)
            x = ep.alpha * x + (1.0f - ep.alpha) * ep.resmat[co];
    } else if (EPI == E_NL) {
        x += ep.bias[n];
        const float c2 = ep.cmat[co];
        x = ep.alpha * (c2 + 0.1f * x) + (1.0f - ep.alpha) * ep.resmat[co];
    }
}

// ============ t128 GEMM: CTA 128x128, 256 thr, warp 64x32, 2 CTAs/SM ============
#define OP_T  (128 * ROWB)             // 18432
#define STGT  (2 * OP_T)               // 36864
#define SMEM_T (NSTG * STGT)           // 110592 -> 2 CTAs/SM co-resident

template <int EPI>
__global__ void __launch_bounds__(256, 2) gemm_t128(
    const float* __restrict__ A, int lda,
    const float* __restrict__ W, int ldb,
    float* __restrict__ C, int ldc, int K, Epi ep)
{
    extern __shared__ __align__(16) char dyns[];
    const uint32_t sbase = smem_u32(dyns);

    const int tid  = threadIdx.x;
    const int wid  = tid >> 5, lane = tid & 31;
    const int m0   = blockIdx.y * 128;
    const int n0   = blockIdx.x * 128;
    const int wm   = (wid >> 2) * 64;     // 0 / 64
    const int wn   = (wid & 3) * 32;      // 0..96

    const int iters = K / 32;

    const int crow = tid >> 3;            // 0..31
    const int ccol = (tid & 7) * 16;
    const int gcol = (tid & 7) * 4;

    auto load_stage = [&](int s, int it) {
        const int ko = it * 32;
        const uint32_t smA = sbase + (uint32_t)s * STGT;
        const uint32_t smB = smA + OP_T;
        const float* ga = A + (size_t)(m0 + crow) * lda + ko + gcol;
        const float* gb = W + (size_t)(n0 + crow) * ldb + ko + gcol;
#pragma unroll
        for (int i = 0; i < 4; i++)
            CP_ASYNC16(smA + (uint32_t)(crow + i * 32) * ROWB + ccol, ga + (size_t)(i * 32) * lda);
#pragma unroll
        for (int i = 0; i < 4; i++)
            CP_ASYNC16(smB + (uint32_t)(crow + i * 32) * ROWB + ccol, gb + (size_t)(i * 32) * ldb);
        CP_COMMIT();
    };

    float acc[4][4][4];
#pragma unroll
    for (int i = 0; i < 4; i++)
#pragma unroll
        for (int j = 0; j < 4; j++)
#pragma unroll
            for (int q = 0; q < 4; q++) acc[i][j][q] = 0.0f;

    load_stage(0, 0);
    load_stage(1, 1);

    const int lr = lane & 15, lc = lane >> 4;

    for (int it = 0; it < iters; ++it) {
        if (it == iters - 1) { CP_WAIT0(); } else { CP_WAIT1(); }
        __syncthreads();
        if (it + 2 < iters) load_stage((it + 2) % NSTG, it + 2);

        const uint32_t smA = sbase + (uint32_t)(it % NSTG) * STGT;
        const uint32_t smB = smA + OP_T;

#pragma unroll
        for (int ks = 0; ks < 4; ks++) {
            uint32_t a[4][4], b[2][4];
#pragma unroll
            for (int mt = 0; mt < 4; mt++) {
                LDSM_X4(a[mt], smA + (uint32_t)(wm + mt * 16 + lr) * ROWB + ks * 32 + lc * 16);
#pragma unroll
                for (int q = 0; q < 4; q++) CVT_TF32(a[mt][q]);
            }
#pragma unroll
            for (int bt = 0; bt < 2; bt++)
                LDSM_X4(b[bt], smB + (uint32_t)(wn + bt * 16 + lr) * ROWB + ks * 32 + lc * 16);
#pragma unroll
            for (int mt = 0; mt < 4; mt++)
#pragma unroll
                for (int nt = 0; nt < 4; nt++)
                    MMA_TF32(acc[mt][nt], a[mt], b[nt >> 1][nt & 1], b[nt >> 1][(nt & 1) + 2]);
        }
    }

    const int gid = lane >> 2, t4 = lane & 3;
#pragma unroll
    for (int mt = 0; mt < 4; mt++) {
#pragma unroll
        for (int half = 0; half < 2; half++) {
            const int m = m0 + wm + mt * 16 + gid + half * 8;
#pragma unroll
            for (int nt = 0; nt < 4; nt++) {
                const int n = n0 + wn + nt * 8 + t4 * 2;
                const size_t co = (size_t)m * ldc + n;
                float x0 = acc[mt][nt][half * 2];
                float x1 = acc[mt][nt][half * 2 + 1];
                epi_apply<EPI>(x0, n, co, ep);
                epi_apply<EPI>(x1, n + 1, co + 1, ep);
                *(float2*)&C[co] = make_float2(x0, x1);
            }
        }
    }
}

// ============ n256 GEMM: CTA 128x256, 256 thr, warp 64x64, fused row-norm =======
#define OP_An (128 * ROWB)
#define OP_Bn (256 * ROWB)
#define STGN  (OP_An + OP_Bn)          // 55296 -> 3* = 165888
#define SMEM_N (NSTG * STGN)
#define SV_STRIDE 260

template <int EPI>
__global__ void __launch_bounds__(256, 1) gemm_norm(
    const float* __restrict__ A, int lda,
    const float* __restrict__ W, int ldb,
    float* __restrict__ C, int K, Epi ep)
{
    extern __shared__ __align__(16) char dyns[];
    const uint32_t sbase = smem_u32(dyns);

    const int tid  = threadIdx.x;
    const int wid  = tid >> 5, lane = tid & 31;
    const int m0   = blockIdx.x * 128;
    const int wm   = (wid >> 2) * 64;      // 0 / 64
    const int wn   = (wid & 3) * 64;       // 0..192

    const int iters = K / 32;

    const int crow = tid >> 3;             // 0..31
    const int ccol = (tid & 7) * 16;
    const int gcol = (tid & 7) * 4;

    auto load_stage = [&](int s, int it) {
        const int ko = it * 32;
        const uint32_t smA = sbase + (uint32_t)s * STGN;
        const uint32_t smB = smA + OP_An;
        const float* ga = A + (size_t)(m0 + crow) * lda + ko + gcol;
        const float* gb = W + (size_t)crow * ldb + ko + gcol;
#pragma unroll
        for (int i = 0; i < 4; i++)
            CP_ASYNC16(smA + (uint32_t)(crow + i * 32) * ROWB + ccol, ga + (size_t)(i * 32) * lda);
#pragma unroll
        for (int i = 0; i < 8; i++)
            CP_ASYNC16(smB + (uint32_t)(crow + i * 32) * ROWB + ccol, gb + (size_t)(i * 32) * ldb);
        CP_COMMIT();
    };

    float acc[4][8][4];
#pragma unroll
    for (int i = 0; i < 4; i++)
#pragma unroll
        for (int j = 0; j < 8; j++)
#pragma unroll
            for (int q = 0; q < 4; q++) acc[i][j][q] = 0.0f;

    load_stage(0, 0);
    load_stage(1, 1);

    const int lr = lane & 15, lc = lane >> 4;

    for (int it = 0; it < iters; ++it) {
        if (it == iters - 1) { CP_WAIT0(); } else { CP_WAIT1(); }
        __syncthreads();
        if (it + 2 < iters) load_stage((it + 2) % NSTG, it + 2);

        const uint32_t smA = sbase + (uint32_t)(it % NSTG) * STGN;
        const uint32_t smB = smA + OP_An;

#pragma unroll
        for (int ks = 0; ks < 4; ks++) {
            uint32_t a[4][4], b[4][4];
#pragma unroll
            for (int mt = 0; mt < 4; mt++) {
                LDSM_X4(a[mt], smA + (uint32_t)(wm + mt * 16 + lr) * ROWB + ks * 32 + lc * 16);
#pragma unroll
                for (int q = 0; q < 4; q++) CVT_TF32(a[mt][q]);
            }
#pragma unroll
            for (int bt = 0; bt < 4; bt++)
                LDSM_X4(b[bt], smB + (uint32_t)(wn + bt * 16 + lr) * ROWB + ks * 32 + lc * 16);
#pragma unroll
            for (int mt = 0; mt < 4; mt++)
#pragma unroll
                for (int nt = 0; nt < 8; nt++)
                    MMA_TF32(acc[mt][nt], a[mt], b[nt >> 1][nt & 1], b[nt >> 1][(nt & 1) + 2]);
        }
    }

    const int gid = lane >> 2, t4 = lane & 3;

    // stage epi-applied values into (now dead) pipeline smem, row-norm, tanh
    float* sv = (float*)dyns;
    __syncthreads();   // all ldmatrix reads done before overwrite
#pragma unroll
    for (int mt = 0; mt < 4; mt++) {
#pragma unroll
        for (int half = 0; half < 2; half++) {
            const int ml = wm + mt * 16 + gid + half * 8;   // 0..127 local row
            const int m  = m0 + ml;
#pragma unroll
            for (int nt = 0; nt < 8; nt++) {
                const int n = wn + nt * 8 + t4 * 2;
                const size_t co = (size_t)m * QD + n;
                float x0 = acc[mt][nt][half * 2];
                float x1 = acc[mt][nt][half * 2 + 1];
                epi_apply<EPI>(x0, n, co, ep);
                epi_apply<EPI>(x1, n + 1, co + 1, ep);
                *(float2*)&sv[ml * SV_STRIDE + n] = make_float2(x0, x1);
            }
        }
    }
    __syncthreads();
    if (tid < 128) {
        const float* r = &sv[tid * SV_STRIDE];
        float s = 0.0f;
#pragma unroll 16
        for (int c = 0; c < 256; c += 4) {
            const float4 v = *(const float4*)&r[c];
            s += v.x * v.x + v.y * v.y + v.z * v.z + v.w * v.w;
        }
        sv[tid * SV_STRIDE + 256] = 1.0f / (sqrtf(s) + 1e-8f);
    }
    __syncthreads();
#pragma unroll 1
    for (int i = 0; i < 32; i++) {
        const int idx = i * 1024 + tid * 4;
        const int row = idx >> 8, col = idx & 255;
        const float inv = sv[row * SV_STRIDE + 256];
        const float4 v = *(const float4*)&sv[row * SV_STRIDE + col];
        *(float4*)&C[(size_t)(m0 + row) * QD + col] =
            make_float4(tanh_fast(v.x * inv), tanh_fast(v.y * inv),
                        tanh_fast(v.z * inv), tanh_fast(v.w * inv));
    }
}

// ---------------- LayerNorm(768) + exact gelu, in place -------------------------
__global__ void ln_gelu_k(float* __restrict__ h,
                          const float* __restrict__ w,
                          const float* __restrict__ b)
{
    const int row = blockIdx.x;
    float* hr = h + (size_t)row * 768;
    const int t = threadIdx.x;

    const float v0 = hr[t], v1 = hr[t + 256], v2 = hr[t + 512];
    float s  = v0 + v1 + v2;
    float ss = v0 * v0 + v1 * v1 + v2 * v2;
#pragma unroll
    for (int o = 16; o > 0; o >>= 1) {
        s  += __shfl_down_sync(0xffffffffu, s, o);
        ss += __shfl_down_sync(0xffffffffu, ss, o);
    }
    __shared__ float rs[8], rss[8], mu_s, rstd_s;
    const int lane = t & 31, wp = t >> 5;
    if (lane == 0) { rs[wp] = s; rss[wp] = ss; }
    __syncthreads();
    if (t == 0) {
        float S = 0.0f, SS = 0.0f;
#pragma unroll
        for (int k = 0; k < 8; k++) { S += rs[k]; SS += rss[k]; }
        const float mu = S * (1.0f / 768.0f);
        mu_s = mu;
        rstd_s = rsqrtf(SS * (1.0f / 768.0f) - mu * mu + 1e-5f);
    }
    __syncthreads();
    const float mu = mu_s, rstd = rstd_s;

#pragma unroll
    for (int k = 0; k < 3; k++) {
        const int c = t + k * 256;
        float x = (((k == 0) ? v0 : (k == 1) ? v1 : v2) - mu) * rstd * w[c] + b[c];
        hr[c] = 0.5f * x * (1.0f + erff(x * 0.70710678118654752f));
    }
}

// ---------------- merged weight transpose + tf32 rounding -----------------------
struct ConvEnt { const float* src; int dstoff; int K; int ldsrc; int coloff; int dotanh; int blk0; };
struct ConvTab { ConvEnt e[32]; int n; };

__global__ void conv_all_k(ConvTab tab, float* __restrict__ dst)
{
    const int blk = blockIdx.x;
    int lo = 0;
    for (int i = 0; i < tab.n; i++)
        if (tab.e[i].blk0 <= blk) lo = i;
    const ConvEnt& E = tab.e[lo];
    const int le = (blk - E.blk0) * 256 + threadIdx.x;
    const int n = le / E.K, k = le - n * E.K;
    float v = E.src[(size_t)k * E.ldsrc + E.coloff + n];
    if (E.dotanh) v = tanhf(v);
    dst[E.dstoff + (size_t)n * E.K + k] = tf32r(v);
}

// ---------------- combined attention weight: Wcomb = Wv @ Wo --------------------
__global__ void comb_k(const float* __restrict__ wqkv, const float* __restrict__ bqkv,
                       const float* __restrict__ wo, const float* __restrict__ bo,
                       float* __restrict__ dst, float* __restrict__ bcmb)
{
    const int i = blockIdx.y;         // matrix index 0/1
    const int n = blockIdx.x;         // 0..255
    const int k = threadIdx.x;        // 0..255
    __shared__ float swo[256];
    swo[k] = wo[(size_t)i * 65536 + (size_t)k * 256 + n];
    __syncthreads();
    const float* wv = wqkv + (size_t)i * 196608 + (size_t)k * 768 + 512;
    float s = 0.0f;
#pragma unroll 8
    for (int j = 0; j < 256; j++) s += wv[j] * swo[j];
    dst[(size_t)i * 65536 + (size_t)n * 256 + k] = tf32r(s);
    if (k == 0) {
        float b = 0.0f;
        const float* bv = bqkv + (size_t)i * 768 + 512;
        for (int j = 0; j < 256; j++) b += bv[j] * swo[j];
        bcmb[i * 256 + n] = b + bo[i * 256 + n];
    }
}

__global__ void prep_k(const float* __restrict__ gp, float* __restrict__ lin,
                       float* __restrict__ p3, float* __restrict__ p4,
                       float* __restrict__ p5)
{
    const int i = blockIdx.x * 256 + threadIdx.x;
    if (i < 8 * QD) {
        const float* p = gp + (size_t)i * 6;
        lin[i] = sinf(p[0]) + cosf(p[1]) + tanhf(p[2]);
        p3[i] = p[3]; p4[i] = p[4]; p5[i] = p[5];
    }
}

// ---------------- host ----------------------------------------------------------
template <int EPI>
static void launch_t128(const float* A, int lda, const float* W, int K, int N,
                        float* C, int ldc, const Epi& ep)
{
    dim3 grid(N / 128, BATCH_N / 128);
    gemm_t128<EPI><<<grid, 256, SMEM_T>>>(A, lda, W, K, C, ldc, K, ep);
}

template <int EPI>
static void launch_norm(const float* A, int lda, const float* W, int K,
                        float* C, const Epi& ep)
{
    gemm_norm<EPI><<<BATCH_N / 128, 256, SMEM_N>>>(A, lda, W, K, C, K, ep);
}

// tf32 weight-buffer fp32-element offsets
#define W01T 0
#define W02T 589824
#define W11T 1179648
#define W12T 1572864
#define WCMB 1966080
#define TENT 2228224
#define NW1T 2752512
#define NW2T 3014656

extern "C" void kernel_launch(void* const* d_in, const int* in_sizes, int n_in,
                              void* d_out, int out_size)
{
    (void)in_sizes; (void)n_in; (void)out_size;
    const float* x    = (const float*)d_in[0];
    const float* w01  = (const float*)d_in[1];
    const float* b01  = (const float*)d_in[2];
    const float* lnw  = (const float*)d_in[3];
    const float* lnb  = (const float*)d_in[4];
    const float* w02  = (const float*)d_in[5];
    const float* b02  = (const float*)d_in[6];
    const float* w11  = (const float*)d_in[7];
    const float* b11  = (const float*)d_in[8];
    const float* w12  = (const float*)d_in[9];
    const float* b12  = (const float*)d_in[10];
    const float* wqkv = (const float*)d_in[11];
    const float* bqkv = (const float*)d_in[12];
    const float* wo   = (const float*)d_in[13];
    const float* bo   = (const float*)d_in[14];
    const float* gp   = (const float*)d_in[15];
    const float* ent  = (const float*)d_in[16];
    const float* nw1  = (const float*)d_in[17];
    const float* nb1  = (const float*)d_in[18];
    const float* nw2  = (const float*)d_in[19];
    const float* nb2  = (const float*)d_in[20];

    cudaFuncSetAttribute(gemm_t128<E_BIAS>, cudaFuncAttributeMaxDynamicSharedMemorySize, SMEM_T);
    cudaFuncSetAttribute(gemm_t128<E_SILU>, cudaFuncAttributeMaxDynamicSharedMemorySize, SMEM_T);
    cudaFuncSetAttribute(gemm_t128<E_TANH>, cudaFuncAttributeMaxDynamicSharedMemorySize, SMEM_T);
    cudaFuncSetAttribute(gemm_t128<E_GATE>, cudaFuncAttributeMaxDynamicSharedMemorySize, SMEM_T);
    cudaFuncSetAttribute(gemm_norm<E_GATE>, cudaFuncAttributeMaxDynamicSharedMemorySize, SMEM_N);
    cudaFuncSetAttribute(gemm_norm<E_NL>,   cudaFuncAttributeMaxDynamicSharedMemorySize, SMEM_N);

    float *H, *FB, *GATEB, *WT, *BCMB;
    cudaGetSymbolAddress((void**)&H,     g_h);
    cudaGetSymbolAddress((void**)&FB,    g_f);
    cudaGetSymbolAddress((void**)&WT,    g_wtf);
    cudaGetSymbolAddress((void**)&GATEB, g_gate);
    cudaGetSymbolAddress((void**)&BCMB,  g_bcmb);

    float* F[3];
    for (int k = 0; k < 3; k++) F[k] = FB + (size_t)k * BATCH_N * QD;
    float* LIN = GATEB + 0 * 8 * QD;
    float* P3  = GATEB + 1 * 8 * QD;
    float* P4  = GATEB + 2 * 8 * QD;
    float* P5  = GATEB + 3 * 8 * QD;

    // ---- merged one-time weight transpose/round ----
    {
        ConvTab tab; int ne = 0, blk = 0;
        auto add = [&](const float* src, size_t zs, int ldsrc, int coloff,
                       int dstoff, size_t dzs, int K, int N, int th, int zn) {
            for (int z = 0; z < zn; z++) {
                tab.e[ne] = { src + (size_t)z * zs, (int)(dstoff + (size_t)z * dzs),
                              K, ldsrc, coloff, th, blk };
                blk += (K * N) / 256;
                ne++;
            }
        };
        add(w01, (size_t)QD * 768, 768, 0,   W01T, 196608, QD, 768, 0, 3);
        add(w02, (size_t)768 * QD, QD,  0,   W02T, 196608, 768, QD, 0, 3);
        add(w11, (size_t)QD * 512, 512, 0,   W11T, 131072, QD, 512, 0, 3);
        add(w12, (size_t)512 * QD, QD,  0,   W12T, 131072, 512, QD, 0, 3);
        add(ent, (size_t)QD * QD,  QD,  0,   TENT, 65536, QD, QD, 1, 8);
        add(nw1, (size_t)QD * QD,  QD,  0,   NW1T, 65536, QD, QD, 0, 4);
        add(nw2, (size_t)QD * QD,  QD,  0,   NW2T, 65536, QD, QD, 0, 4);
        tab.n = ne;
        conv_all_k<<<blk, 256>>>(tab, WT);
    }
    comb_k<<<dim3(256, 2), 256>>>(wqkv, bqkv, wo, bo, WT + WCMB, BCMB);
    prep_k<<<8, 256>>>(gp, LIN, P3, P4, P5);

    const float* cur = x;
    int scur = -1;

    for (int li = 0; li < 8; li++) {
        int s0 = -1, s1 = -1;
        for (int k = 0; k < 3; k++)
            if (k != scur) { if (s0 < 0) s0 = k; else if (s1 < 0) s1 = k; }
        float* F0 = F[s0]; float* F1 = F[s1];

        const int t = li % 3;
        const int odd = li & 1;
        const float alpha = (li < 4) ? 0.8f : 0.6f;

        if (t == 0) {
            const int i = li / 3;
            Epi e = {}; e.bias = b01 + i * 768;
            launch_t128<E_BIAS>(cur, QD, WT + W01T + (size_t)i * 196608, QD, 768, H, 768, e);
            ln_gelu_k<<<BATCH_N, 256>>>(H, lnw + i * 768, lnb + i * 768);
            Epi e2 = {}; e2.bias = b02 + i * QD;
            launch_t128<E_BIAS>(H, 768, WT + W02T + (size_t)i * 196608, 768, QD, F0, QD, e2);
        } else if (t == 1) {
            const int i = (li - 1) / 3;
            Epi e = {}; e.bias = b11 + i * 512;
            launch_t128<E_SILU>(cur, QD, WT + W11T + (size_t)i * 131072, QD, 512, H, 512, e);
            Epi e2 = {}; e2.bias = b12 + i * QD;
            launch_t128<E_BIAS>(H, 512, WT + W12T + (size_t)i * 131072, 512, QD, F0, QD, e2);
        } else {
            // attention layer collapsed: cur @ (Wv@Wo) + (bv@Wo + bo)
            const int i = (li - 2) / 3;
            Epi e = {}; e.bias = BCMB + i * QD;
            launch_t128<E_BIAS>(cur, QD, WT + WCMB + (size_t)i * 65536, QD, QD, F0, QD, e);
        }

        // entangle + gate; even layers also blend + row-norm + tanh (final for layer)
        Epi eg = {};
        eg.cmat = F0; eg.resmat = cur;
        eg.lin = LIN + li * QD; eg.p3 = P3 + li * QD;
        eg.p4 = P4 + li * QD;   eg.p5 = P5 + li * QD;
        eg.alpha = alpha; eg.blend = !odd;
        if (!odd) {
            launch_norm<E_GATE>(F0, QD, WT + TENT + (size_t)li * 65536, QD, F1, eg);
            cur = F1; scur = s1;
        } else {
            launch_t128<E_GATE>(F0, QD, WT + TENT + (size_t)li * 65536, QD, QD, F1, QD, eg);
            const int j = li / 2;
            Epi et = {}; et.bias = nb1 + j * QD;
            launch_t128<E_TANH>(F1, QD, WT + NW1T + (size_t)j * 65536, QD, QD, H, QD, et);
            Epi en = {}; en.bias = nb2 + j * QD;
            en.cmat = F1; en.resmat = cur; en.alpha = alpha;
            float* dst = (li == 7) ? (float*)d_out : F1;
            launch_norm<E_NL>(H, QD, WT + NW2T + (size_t)j * 65536, QD, dst, en);
            cur = dst; scur = s1;
        }
    }
}

// round 13
// speedup vs baseline: 1.2079x; 1.0268x over previous
#include <cuda_runtime.h>
#include <cuda_bf16.h>
#include <math.h>
#include <stdint.h>
#include <stddef.h>

#define BATCH_N 65536
#define QD      256

// ---------------- ptx helpers ---------------------------------------------------
__device__ __forceinline__ uint32_t smem_u32(const void* p) {
    uint32_t a;
    asm("{ .reg .u64 t; cvta.to.shared.u64 t, %1; cvt.u32.u64 %0, t; }" : "=r"(a) : "l"(p));
    return a;
}

#define CP_ASYNC16(dst, src) \
    asm volatile("cp.async.cg.shared.global [%0], [%1], 16;" :: "r"(dst), "l"(src) : "memory")
#define CP_COMMIT() asm volatile("cp.async.commit_group;" ::: "memory")
#define CP_WAIT1()  asm volatile("cp.async.wait_group 1;" ::: "memory")
#define CP_WAIT0()  asm volatile("cp.async.wait_group 0;" ::: "memory")

#define LDSM_X4(r, addr) \
    asm volatile("ldmatrix.sync.aligned.m8n8.x4.shared.b16 {%0,%1,%2,%3}, [%4];" \
        : "=r"((r)[0]), "=r"((r)[1]), "=r"((r)[2]), "=r"((r)[3]) : "r"(addr))

#define MMA_TF32(c, a, b0, b1) \
    asm volatile("mma.sync.aligned.m16n8k8.row.col.f32.tf32.tf32.f32 " \
        "{%0,%1,%2,%3}, {%4,%5,%6,%7}, {%8,%9}, {%0,%1,%2,%3};" \
        : "+f"((c)[0]), "+f"((c)[1]), "+f"((c)[2]), "+f"((c)[3]) \
        : "r"((a)[0]), "r"((a)[1]), "r"((a)[2]), "r"((a)[3]), "r"(b0), "r"(b1))

__device__ __forceinline__ float tf32r(float v) {
    asm("cvt.rna.tf32.f32 %0, %0;" : "+f"(v));
    return v;
}

__device__ __forceinline__ float tanh_fast(float x) {
    return 1.0f - 2.0f / (__expf(2.0f * x) + 1.0f);
}

// ---------------- scratch -------------------------------------------------------
static __device__ __align__(16) float g_h[(size_t)BATCH_N * 768];
static __device__ __align__(16) float g_f[3][(size_t)BATCH_N * QD];
static __device__ __align__(16) float g_wtf[3276800];
static __device__ __align__(16) float g_gate[4][8 * QD];
static __device__ __align__(16) float g_bcmb[2 * QD];

struct Epi {
    const float* bias;
    const float* cmat;
    const float* resmat;
    const float* lin; const float* p3; const float* p4; const float* p5;
    float alpha;
    int   blend;
    int   rnd;        // gemm_norm: tf32-round outputs (0 for final d_out)
};

enum { E_BIAS = 0, E_SILU = 1, E_TANH = 2, E_GATE = 3, E_NL = 4 };

#define ROWB 144                       // 128B data + 16B skew
#define NSTG 3

template <int EPI>
__device__ __forceinline__ void epi_apply(float& x, int n, size_t co, const Epi& ep) {
    if (EPI == E_BIAS) {
        x += ep.bias[n];
    } else if (EPI == E_SILU) {
        x += ep.bias[n];
        x = x / (1.0f + __expf(-x));
    } else if (EPI == E_TANH) {
        x += ep.bias[n];
        x = tanh_fast(x);
    } else if (EPI == E_GATE) {
        const float c = ep.cmat[co];
        const float g = (ep.lin[n] * c
                         + 0.5f * __sinf(ep.p3[n] * c + ep.p4[n])
                         + 0.5f * __cosf(ep.p5[n] * c)) * 0.25f;
        x = (c + 0.3f * g + 0.2f * x) * (1.0f / 1.5f);
        if (ep.blend)
            x = ep.alpha * x + (1.0f - ep.alpha) * ep.resmat[co];
    } else if (EPI == E_NL) {
        x += ep.bias[n];
        const float c2 = ep.cmat[co];
        x = ep.alpha * (c2 + 0.1f * x) + (1.0f - ep.alpha) * ep.resmat[co];
    }
}

// ============ t128 GEMM: CTA 128x128, 256 thr, warp 64x32, 2 CTAs/SM ============
// A operands are tf32-pre-rounded at production; outputs are tf32-rounded.
#define OP_T  (128 * ROWB)             // 18432
#define STGT  (2 * OP_T)               // 36864
#define SMEM_T (NSTG * STGT)           // 110592 -> 2 CTAs/SM co-resident

template <int EPI>
__global__ void __launch_bounds__(256, 2) gemm_t128(
    const float* __restrict__ A, int lda,
    const float* __restrict__ W, int ldb,
    float* __restrict__ C, int ldc, int K, Epi ep)
{
    extern __shared__ __align__(16) char dyns[];
    const uint32_t sbase = smem_u32(dyns);

    const int tid  = threadIdx.x;
    const int wid  = tid >> 5, lane = tid & 31;
    const int m0   = blockIdx.y * 128;
    const int n0   = blockIdx.x * 128;
    const int wm   = (wid >> 2) * 64;     // 0 / 64
    const int wn   = (wid & 3) * 32;      // 0..96

    const int iters = K / 32;

    const int crow = tid >> 3;            // 0..31
    const int ccol = (tid & 7) * 16;
    const int gcol = (tid & 7) * 4;

    auto load_stage = [&](int s, int it) {
        const int ko = it * 32;
        const uint32_t smA = sbase + (uint32_t)s * STGT;
        const uint32_t smB = smA + OP_T;
        const float* ga = A + (size_t)(m0 + crow) * lda + ko + gcol;
        const float* gb = W + (size_t)(n0 + crow) * ldb + ko + gcol;
#pragma unroll
        for (int i = 0; i < 4; i++)
            CP_ASYNC16(smA + (uint32_t)(crow + i * 32) * ROWB + ccol, ga + (size_t)(i * 32) * lda);
#pragma unroll
        for (int i = 0; i < 4; i++)
            CP_ASYNC16(smB + (uint32_t)(crow + i * 32) * ROWB + ccol, gb + (size_t)(i * 32) * ldb);
        CP_COMMIT();
    };

    float acc[4][4][4];
#pragma unroll
    for (int i = 0; i < 4; i++)
#pragma unroll
        for (int j = 0; j < 4; j++)
#pragma unroll
            for (int q = 0; q < 4; q++) acc[i][j][q] = 0.0f;

    load_stage(0, 0);
    load_stage(1, 1);

    const int lr = lane & 15, lc = lane >> 4;

    for (int it = 0; it < iters; ++it) {
        if (it == iters - 1) { CP_WAIT0(); } else { CP_WAIT1(); }
        __syncthreads();
        if (it + 2 < iters) load_stage((it + 2) % NSTG, it + 2);

        const uint32_t smA = sbase + (uint32_t)(it % NSTG) * STGT;
        const uint32_t smB = smA + OP_T;

#pragma unroll
        for (int ks = 0; ks < 4; ks++) {
            uint32_t a[4][4], b[2][4];
#pragma unroll
            for (int mt = 0; mt < 4; mt++)
                LDSM_X4(a[mt], smA + (uint32_t)(wm + mt * 16 + lr) * ROWB + ks * 32 + lc * 16);
#pragma unroll
            for (int bt = 0; bt < 2; bt++)
                LDSM_X4(b[bt], smB + (uint32_t)(wn + bt * 16 + lr) * ROWB + ks * 32 + lc * 16);
#pragma unroll
            for (int mt = 0; mt < 4; mt++)
#pragma unroll
                for (int nt = 0; nt < 4; nt++)
                    MMA_TF32(acc[mt][nt], a[mt], b[nt >> 1][nt & 1], b[nt >> 1][(nt & 1) + 2]);
        }
    }

    const int gid = lane >> 2, t4 = lane & 3;
#pragma unroll
    for (int mt = 0; mt < 4; mt++) {
#pragma unroll
        for (int half = 0; half < 2; half++) {
            const int m = m0 + wm + mt * 16 + gid + half * 8;
#pragma unroll
            for (int nt = 0; nt < 4; nt++) {
                const int n = n0 + wn + nt * 8 + t4 * 2;
                const size_t co = (size_t)m * ldc + n;
                float x0 = acc[mt][nt][half * 2];
                float x1 = acc[mt][nt][half * 2 + 1];
                epi_apply<EPI>(x0, n, co, ep);
                epi_apply<EPI>(x1, n + 1, co + 1, ep);
                *(float2*)&C[co] = make_float2(tf32r(x0), tf32r(x1));
            }
        }
    }
}

// ============ n256 GEMM: CTA 128x256, 256 thr, warp 64x64, fused row-norm =======
#define OP_An (128 * ROWB)
#define OP_Bn (256 * ROWB)
#define STGN  (OP_An + OP_Bn)          // 55296 -> 3* = 165888
#define SMEM_N (NSTG * STGN)
#define SV_STRIDE 260

template <int EPI>
__global__ void __launch_bounds__(256, 1) gemm_norm(
    const float* __restrict__ A, int lda,
    const float* __restrict__ W, int ldb,
    float* __restrict__ C, int K, Epi ep)
{
    extern __shared__ __align__(16) char dyns[];
    const uint32_t sbase = smem_u32(dyns);

    const int tid  = threadIdx.x;
    const int wid  = tid >> 5, lane = tid & 31;
    const int m0   = blockIdx.x * 128;
    const int wm   = (wid >> 2) * 64;      // 0 / 64
    const int wn   = (wid & 3) * 64;       // 0..192

    const int iters = K / 32;

    const int crow = tid >> 3;             // 0..31
    const int ccol = (tid & 7) * 16;
    const int gcol = (tid & 7) * 4;

    auto load_stage = [&](int s, int it) {
        const int ko = it * 32;
        const uint32_t smA = sbase + (uint32_t)s * STGN;
        const uint32_t smB = smA + OP_An;
        const float* ga = A + (size_t)(m0 + crow) * lda + ko + gcol;
        const float* gb = W + (size_t)crow * ldb + ko + gcol;
#pragma unroll
        for (int i = 0; i < 4; i++)
            CP_ASYNC16(smA + (uint32_t)(crow + i * 32) * ROWB + ccol, ga + (size_t)(i * 32) * lda);
#pragma unroll
        for (int i = 0; i < 8; i++)
            CP_ASYNC16(smB + (uint32_t)(crow + i * 32) * ROWB + ccol, gb + (size_t)(i * 32) * ldb);
        CP_COMMIT();
    };

    float acc[4][8][4];
#pragma unroll
    for (int i = 0; i < 4; i++)
#pragma unroll
        for (int j = 0; j < 8; j++)
#pragma unroll
            for (int q = 0; q < 4; q++) acc[i][j][q] = 0.0f;

    load_stage(0, 0);
    load_stage(1, 1);

    const int lr = lane & 15, lc = lane >> 4;

    for (int it = 0; it < iters; ++it) {
        if (it == iters - 1) { CP_WAIT0(); } else { CP_WAIT1(); }
        __syncthreads();
        if (it + 2 < iters) load_stage((it + 2) % NSTG, it + 2);

        const uint32_t smA = sbase + (uint32_t)(it % NSTG) * STGN;
        const uint32_t smB = smA + OP_An;

#pragma unroll
        for (int ks = 0; ks < 4; ks++) {
            uint32_t a[4][4], b[4][4];
#pragma unroll
            for (int mt = 0; mt < 4; mt++)
                LDSM_X4(a[mt], smA + (uint32_t)(wm + mt * 16 + lr) * ROWB + ks * 32 + lc * 16);
#pragma unroll
            for (int bt = 0; bt < 4; bt++)
                LDSM_X4(b[bt], smB + (uint32_t)(wn + bt * 16 + lr) * ROWB + ks * 32 + lc * 16);
#pragma unroll
            for (int mt = 0; mt < 4; mt++)
#pragma unroll
                for (int nt = 0; nt < 8; nt++)
                    MMA_TF32(acc[mt][nt], a[mt], b[nt >> 1][nt & 1], b[nt >> 1][(nt & 1) + 2]);
        }
    }

    const int gid = lane >> 2, t4 = lane & 3;

    // stage epi-applied values into (now dead) pipeline smem, row-norm, tanh
    float* sv = (float*)dyns;
    __syncthreads();   // all ldmatrix reads done before overwrite
#pragma unroll
    for (int mt = 0; mt < 4; mt++) {
#pragma unroll
        for (int half = 0; half < 2; half++) {
            const int ml = wm + mt * 16 + gid + half * 8;   // 0..127 local row
            const int m  = m0 + ml;
#pragma unroll
            for (int nt = 0; nt < 8; nt++) {
                const int n = wn + nt * 8 + t4 * 2;
                const size_t co = (size_t)m * QD + n;
                float x0 = acc[mt][nt][half * 2];
                float x1 = acc[mt][nt][half * 2 + 1];
                epi_apply<EPI>(x0, n, co, ep);
                epi_apply<EPI>(x1, n + 1, co + 1, ep);
                *(float2*)&sv[ml * SV_STRIDE + n] = make_float2(x0, x1);
            }
        }
    }
    __syncthreads();
    if (tid < 128) {
        const float* r = &sv[tid * SV_STRIDE];
        float s = 0.0f;
#pragma unroll 16
        for (int c = 0; c < 256; c += 4) {
            const float4 v = *(const float4*)&r[c];
            s += v.x * v.x + v.y * v.y + v.z * v.z + v.w * v.w;
        }
        sv[tid * SV_STRIDE + 256] = 1.0f / (sqrtf(s) + 1e-8f);
    }
    __syncthreads();
    if (ep.rnd) {
#pragma unroll 1
        for (int i = 0; i < 32; i++) {
            const int idx = i * 1024 + tid * 4;
            const int row = idx >> 8, col = idx & 255;
            const float inv = sv[row * SV_STRIDE + 256];
            const float4 v = *(const float4*)&sv[row * SV_STRIDE + col];
            *(float4*)&C[(size_t)(m0 + row) * QD + col] =
                make_float4(tf32r(tanh_fast(v.x * inv)), tf32r(tanh_fast(v.y * inv)),
                            tf32r(tanh_fast(v.z * inv)), tf32r(tanh_fast(v.w * inv)));
        }
    } else {
#pragma unroll 1
        for (int i = 0; i < 32; i++) {
            const int idx = i * 1024 + tid * 4;
            const int row = idx >> 8, col = idx & 255;
            const float inv = sv[row * SV_STRIDE + 256];
            const float4 v = *(const float4*)&sv[row * SV_STRIDE + col];
            *(float4*)&C[(size_t)(m0 + row) * QD + col] =
                make_float4(tanh_fast(v.x * inv), tanh_fast(v.y * inv),
                            tanh_fast(v.z * inv), tanh_fast(v.w * inv));
        }
    }
}

// ---------------- LayerNorm(768) + exact gelu, in place (tf32-rounded out) ------
__global__ void ln_gelu_k(float* __restrict__ h,
                          const float* __restrict__ w,
                          const float* __restrict__ b)
{
    const int row = blockIdx.x;
    float* hr = h + (size_t)row * 768;
    const int t = threadIdx.x;

    const float v0 = hr[t], v1 = hr[t + 256], v2 = hr[t + 512];
    float s  = v0 + v1 + v2;
    float ss = v0 * v0 + v1 * v1 + v2 * v2;
#pragma unroll
    for (int o = 16; o > 0; o >>= 1) {
        s  += __shfl_down_sync(0xffffffffu, s, o);
        ss += __shfl_down_sync(0xffffffffu, ss, o);
    }
    __shared__ float rs[8], rss[8], mu_s, rstd_s;
    const int lane = t & 31, wp = t >> 5;
    if (lane == 0) { rs[wp] = s; rss[wp] = ss; }
    __syncthreads();
    if (t == 0) {
        float S = 0.0f, SS = 0.0f;
#pragma unroll
        for (int k = 0; k < 8; k++) { S += rs[k]; SS += rss[k]; }
        const float mu = S * (1.0f / 768.0f);
        mu_s = mu;
        rstd_s = rsqrtf(SS * (1.0f / 768.0f) - mu * mu + 1e-5f);
    }
    __syncthreads();
    const float mu = mu_s, rstd = rstd_s;

#pragma unroll
    for (int k = 0; k < 3; k++) {
        const int c = t + k * 256;
        float x = (((k == 0) ? v0 : (k == 1) ? v1 : v2) - mu) * rstd * w[c] + b[c];
        hr[c] = tf32r(0.5f * x * (1.0f + erff(x * 0.70710678118654752f)));
    }
}

// ---------------- merged weight transpose + tf32 rounding -----------------------
struct ConvEnt { const float* src; int dstoff; int K; int ldsrc; int coloff; int dotanh; int blk0; };
struct ConvTab { ConvEnt e[32]; int n; };

__global__ void conv_all_k(ConvTab tab, float* __restrict__ dst)
{
    const int blk = blockIdx.x;
    int lo = 0;
    for (int i = 0; i < tab.n; i++)
        if (tab.e[i].blk0 <= blk) lo = i;
    const ConvEnt& E = tab.e[lo];
    const int le = (blk - E.blk0) * 256 + threadIdx.x;
    const int n = le / E.K, k = le - n * E.K;
    float v = E.src[(size_t)k * E.ldsrc + E.coloff + n];
    if (E.dotanh) v = tanhf(v);
    dst[E.dstoff + (size_t)n * E.K + k] = tf32r(v);
}

// ---------------- x -> tf32-rounded copy ----------------------------------------
__global__ void conv_x_k(const float* __restrict__ x, float* __restrict__ o)
{
    const size_t i = (size_t)blockIdx.x * 256 + threadIdx.x;
    o[i] = tf32r(x[i]);
}

// ---------------- combined attention weight: Wcomb = Wv @ Wo --------------------
__global__ void comb_k(const float* __restrict__ wqkv, const float* __restrict__ bqkv,
                       const float* __restrict__ wo, const float* __restrict__ bo,
                       float* __restrict__ dst, float* __restrict__ bcmb)
{
    const int i = blockIdx.y;         // matrix index 0/1
    const int n = blockIdx.x;         // 0..255
    const int k = threadIdx.x;        // 0..255
    __shared__ float swo[256];
    swo[k] = wo[(size_t)i * 65536 + (size_t)k * 256 + n];
    __syncthreads();
    const float* wv = wqkv + (size_t)i * 196608 + (size_t)k * 768 + 512;
    float s = 0.0f;
#pragma unroll 8
    for (int j = 0; j < 256; j++) s += wv[j] * swo[j];
    dst[(size_t)i * 65536 + (size_t)n * 256 + k] = tf32r(s);
    if (k == 0) {
        float b = 0.0f;
        const float* bv = bqkv + (size_t)i * 768 + 512;
        for (int j = 0; j < 256; j++) b += bv[j] * swo[j];
        bcmb[i * 256 + n] = b + bo[i * 256 + n];
    }
}

__global__ void prep_k(const float* __restrict__ gp, float* __restrict__ lin,
                       float* __restrict__ p3, float* __restrict__ p4,
                       float* __restrict__ p5)
{
    const int i = blockIdx.x * 256 + threadIdx.x;
    if (i < 8 * QD) {
        const float* p = gp + (size_t)i * 6;
        lin[i] = sinf(p[0]) + cosf(p[1]) + tanhf(p[2]);
        p3[i] = p[3]; p4[i] = p[4]; p5[i] = p[5];
    }
}

// ---------------- host ----------------------------------------------------------
template <int EPI>
static void launch_t128(const float* A, int lda, const float* W, int K, int N,
                        float* C, int ldc, const Epi& ep)
{
    dim3 grid(N / 128, BATCH_N / 128);
    gemm_t128<EPI><<<grid, 256, SMEM_T>>>(A, lda, W, K, C, ldc, K, ep);
}

template <int EPI>
static void launch_norm(const float* A, int lda, const float* W, int K,
                        float* C, const Epi& ep)
{
    gemm_norm<EPI><<<BATCH_N / 128, 256, SMEM_N>>>(A, lda, W, K, C, K, ep);
}

// tf32 weight-buffer fp32-element offsets
#define W01T 0
#define W02T 589824
#define W11T 1179648
#define W12T 1572864
#define WCMB 1966080
#define TENT 2228224
#define NW1T 2752512
#define NW2T 3014656

extern "C" void kernel_launch(void* const* d_in, const int* in_sizes, int n_in,
                              void* d_out, int out_size)
{
    (void)in_sizes; (void)n_in; (void)out_size;
    const float* x    = (const float*)d_in[0];
    const float* w01  = (const float*)d_in[1];
    const float* b01  = (const float*)d_in[2];
    const float* lnw  = (const float*)d_in[3];
    const float* lnb  = (const float*)d_in[4];
    const float* w02  = (const float*)d_in[5];
    const float* b02  = (const float*)d_in[6];
    const float* w11  = (const float*)d_in[7];
    const float* b11  = (const float*)d_in[8];
    const float* w12  = (const float*)d_in[9];
    const float* b12  = (const float*)d_in[10];
    const float* wqkv = (const float*)d_in[11];
    const float* bqkv = (const float*)d_in[12];
    const float* wo   = (const float*)d_in[13];
    const float* bo   = (const float*)d_in[14];
    const float* gp   = (const float*)d_in[15];
    const float* ent  = (const float*)d_in[16];
    const float* nw1  = (const float*)d_in[17];
    const float* nb1  = (const float*)d_in[18];
    const float* nw2  = (const float*)d_in[19];
    const float* nb2  = (const float*)d_in[20];

    cudaFuncSetAttribute(gemm_t128<E_BIAS>, cudaFuncAttributeMaxDynamicSharedMemorySize, SMEM_T);
    cudaFuncSetAttribute(gemm_t128<E_SILU>, cudaFuncAttributeMaxDynamicSharedMemorySize, SMEM_T);
    cudaFuncSetAttribute(gemm_t128<E_TANH>, cudaFuncAttributeMaxDynamicSharedMemorySize, SMEM_T);
    cudaFuncSetAttribute(gemm_t128<E_GATE>, cudaFuncAttributeMaxDynamicSharedMemorySize, SMEM_T);
    cudaFuncSetAttribute(gemm_norm<E_GATE>, cudaFuncAttributeMaxDynamicSharedMemorySize, SMEM_N);
    cudaFuncSetAttribute(gemm_norm<E_NL>,   cudaFuncAttributeMaxDynamicSharedMemorySize, SMEM_N);

    float *H, *FB, *GATEB, *WT, *BCMB;
    cudaGetSymbolAddress((void**)&H,     g_h);
    cudaGetSymbolAddress((void**)&FB,    g_f);
    cudaGetSymbolAddress((void**)&WT,    g_wtf);
    cudaGetSymbolAddress((void**)&GATEB, g_gate);
    cudaGetSymbolAddress((void**)&BCMB,  g_bcmb);

    float* F[3];
    for (int k = 0; k < 3; k++) F[k] = FB + (size_t)k * BATCH_N * QD;
    float* LIN = GATEB + 0 * 8 * QD;
    float* P3  = GATEB + 1 * 8 * QD;
    float* P4  = GATEB + 2 * 8 * QD;
    float* P5  = GATEB + 3 * 8 * QD;

    // ---- merged one-time weight transpose/round ----
    {
        ConvTab tab; int ne = 0, blk = 0;
        auto add = [&](const float* src, size_t zs, int ldsrc, int coloff,
                       int dstoff, size_t dzs, int K, int N, int th, int zn) {
            for (int z = 0; z < zn; z++) {
                tab.e[ne] = { src + (size_t)z * zs, (int)(dstoff + (size_t)z * dzs),
                              K, ldsrc, coloff, th, blk };
                blk += (K * N) / 256;
                ne++;
            }
        };
        add(w01, (size_t)QD * 768, 768, 0,   W01T, 196608, QD, 768, 0, 3);
        add(w02, (size_t)768 * QD, QD,  0,   W02T, 196608, 768, QD, 0, 3);
        add(w11, (size_t)QD * 512, 512, 0,   W11T, 131072, QD, 512, 0, 3);
        add(w12, (size_t)512 * QD, QD,  0,   W12T, 131072, 512, QD, 0, 3);
        add(ent, (size_t)QD * QD,  QD,  0,   TENT, 65536, QD, QD, 1, 8);
        add(nw1, (size_t)QD * QD,  QD,  0,   NW1T, 65536, QD, QD, 0, 4);
        add(nw2, (size_t)QD * QD,  QD,  0,   NW2T, 65536, QD, QD, 0, 4);
        tab.n = ne;
        conv_all_k<<<blk, 256>>>(tab, WT);
    }
    comb_k<<<dim3(256, 2), 256>>>(wqkv, bqkv, wo, bo, WT + WCMB, BCMB);
    prep_k<<<8, 256>>>(gp, LIN, P3, P4, P5);
    conv_x_k<<<BATCH_N, 256>>>(x, F[2]);     // tf32-rounded x for layer-0 GEMM A

    const float* cur  = x;      // residual (unrounded)
    const float* curA = F[2];   // GEMM A operand (rounded)
    int scur = -1;              // F[2] safe: first reused as F1 at li=1, after layer-0 A use

    for (int li = 0; li < 8; li++) {
        int s0 = -1, s1 = -1;
        for (int k = 0; k < 3; k++)
            if (k != scur) { if (s0 < 0) s0 = k; else if (s1 < 0) s1 = k; }
        float* F0 = F[s0]; float* F1 = F[s1];

        const int t = li % 3;
        const int odd = li & 1;
        const float alpha = (li < 4) ? 0.8f : 0.6f;

        if (t == 0) {
            const int i = li / 3;
            Epi e = {}; e.bias = b01 + i * 768;
            launch_t128<E_BIAS>(curA, QD, WT + W01T + (size_t)i * 196608, QD, 768, H, 768, e);
            ln_gelu_k<<<BATCH_N, 256>>>(H, lnw + i * 768, lnb + i * 768);
            Epi e2 = {}; e2.bias = b02 + i * QD;
            launch_t128<E_BIAS>(H, 768, WT + W02T + (size_t)i * 196608, 768, QD, F0, QD, e2);
        } else if (t == 1) {
            const int i = (li - 1) / 3;
            Epi e = {}; e.bias = b11 + i * 512;
            launch_t128<E_SILU>(curA, QD, WT + W11T + (size_t)i * 131072, QD, 512, H, 512, e);
            Epi e2 = {}; e2.bias = b12 + i * QD;
            launch_t128<E_BIAS>(H, 512, WT + W12T + (size_t)i * 131072, 512, QD, F0, QD, e2);
        } else {
            // attention layer collapsed: cur @ (Wv@Wo) + (bv@Wo + bo)
            const int i = (li - 2) / 3;
            Epi e = {}; e.bias = BCMB + i * QD;
            launch_t128<E_BIAS>(curA, QD, WT + WCMB + (size_t)i * 65536, QD, QD, F0, QD, e);
        }

        // entangle + gate; even layers also blend + row-norm + tanh (final for layer)
        Epi eg = {};
        eg.cmat = F0; eg.resmat = cur;
        eg.lin = LIN + li * QD; eg.p3 = P3 + li * QD;
        eg.p4 = P4 + li * QD;   eg.p5 = P5 + li * QD;
        eg.alpha = alpha; eg.blend = !odd; eg.rnd = 1;
        if (!odd) {
            launch_norm<E_GATE>(F0, QD, WT + TENT + (size_t)li * 65536, QD, F1, eg);
            cur = F1; curA = F1; scur = s1;
        } else {
            launch_t128<E_GATE>(F0, QD, WT + TENT + (size_t)li * 65536, QD, QD, F1, QD, eg);
            const int j = li / 2;
            Epi et = {}; et.bias = nb1 + j * QD;
            launch_t128<E_TANH>(F1, QD, WT + NW1T + (size_t)j * 65536, QD, QD, H, QD, et);
            Epi en = {}; en.bias = nb2 + j * QD;
            en.cmat = F1; en.resmat = cur; en.alpha = alpha;
            en.rnd = (li != 7);
            float* dst = (li == 7) ? (float*)d_out : F1;
            launch_norm<E_NL>(H, QD, WT + NW2T + (size_t)j * 65536, QD, dst, en);
            cur = dst; curA = dst; scur = s1;
        }
    }
}